// round 9
// baseline (speedup 1.0000x reference)
#include <cuda_runtime.h>
#include <cstdint>
#include <cstddef>

#define GRIDB 288
#define NTHR  256
#define Bsz   128
#define Tlen  512
#define Vocab 512
#define Emb   512
#define Hid   1024
#define G4    4096

// dynamic smem: 2 stages x (sA 128x18 u64 + sW 128x18 u64)
#define SROW   18
#define STILE  (128 * SROW)          // u64 elements per tile image
#define SSTAGE (2 * STILE)           // A + W
#define SMEM_DYN (2 * SSTAGE * 8)    // bytes (73728)

// ---------------- device scratch (static; no runtime allocation) ----------------
__device__ float g_X[Bsz * Emb];
__device__ float g_H0[Bsz * Hid];
__device__ float g_C0[Bsz * Hid];
__device__ float g_H1[Bsz * Hid];
__device__ float g_C1[Bsz * Hid];
__device__ float g_part[9 * Bsz * G4];        // layer GEMM K-chunk partials
__device__ float g_lpart[16 * Bsz * Vocab];   // logits K-chunk partials
__device__ float g_bias0[G4];
__device__ float g_bias1[G4];
__device__ unsigned char g_dec[Tlen * Bsz];

// ---------------- software grid barrier (generation-continued) ----------------
__device__ unsigned long long g_cnt;
__device__ volatile unsigned long long g_gen;

__device__ __forceinline__ void grid_sync(unsigned long long& lgen) {
    __threadfence();
    __syncthreads();
    if (threadIdx.x == 0) {
        lgen += 1ULL;
        unsigned long long a = atomicAdd(&g_cnt, 1ULL) + 1ULL;
        if (a == lgen * (unsigned long long)GRIDB) {
            g_gen = lgen;
            __threadfence();
        } else {
            while (g_gen < lgen) { __nanosleep(32); }
            __threadfence();
        }
    }
    __syncthreads();
}

// ---------------- small helpers ----------------
__device__ __forceinline__ unsigned rotl32(unsigned x, int d) {
    return (x << d) | (x >> (32 - d));
}
__device__ __forceinline__ float sigm(float x) { return 1.0f / (1.0f + expf(-x)); }

__device__ __forceinline__ uint32_t tf32c(float f) {
    uint32_t r;
    asm("cvt.rna.tf32.f32 %0, %1;" : "=r"(r) : "f"(f));
    return r;
}
// Dekker split: v = tf32(v) + tf32(residual) + O(2^-23 v); both parts exact fp32.
__device__ __forceinline__ unsigned long long pksplit(float v) {
    uint32_t u0 = tf32c(v);
    uint32_t u1 = tf32c(v - __uint_as_float(u0));
    return (unsigned long long)u0 | ((unsigned long long)u1 << 32);
}

__device__ __forceinline__ void mma_tf32(float& d0, float& d1, float& d2, float& d3,
                                         uint32_t a0, uint32_t a1, uint32_t a2, uint32_t a3,
                                         uint32_t b0, uint32_t b1) {
    asm volatile(
        "mma.sync.aligned.m16n8k8.row.col.f32.tf32.tf32.f32 "
        "{%0,%1,%2,%3}, {%4,%5,%6,%7}, {%8,%9}, {%0,%1,%2,%3};"
        : "+f"(d0), "+f"(d1), "+f"(d2), "+f"(d3)
        : "r"(a0), "r"(a1), "r"(a2), "r"(a3), "r"(b0), "r"(b1));
}

// k-permutation inside a 16-k tile: makes frag cols (c, c+4) adjacent u64 pairs
__device__ __forceinline__ int kperm(int k) {
    return (k & 8) | ((k & 3) << 1) | ((k >> 2) & 1);
}

// ---------------- tf32 2-split 4-term MMA GEMM over a virtual concatenated K ----
// Output tile: 128 x 128 at column n0. Virtual K in 16-k tiles, two segments.
// A: [128, lda] row-major; W: [N, ldw] row-major (k contiguous). fp32 -> Cp.
__device__ void mma_gemm(unsigned long long* sm,
    const float* __restrict__ A0, int lda0, const float* __restrict__ W0, int ldw0,
    int segTiles0,
    const float* __restrict__ A1, int lda1, const float* __restrict__ W1, int ldw1,
    int ktB, int ktE, int n0, float* __restrict__ Cp, int ldc)
{
    const int tid  = threadIdx.x;
    const int warp = tid >> 5, lane = tid & 31;
    const int wm = warp >> 2, wn = warp & 3;       // 2 x 4 warp grid, warp tile 64x32
    const int gid = lane >> 2, cc = lane & 3;

    float4 ra[2], rw[2];

    auto ldg = [&](int kt) {
        const float* A; const float* W; int lda, ldw, kl;
        if (kt < segTiles0) { A = A0; lda = lda0; W = W0; ldw = ldw0; kl = kt * 16; }
        else                { A = A1; lda = lda1; W = W1; ldw = ldw1; kl = (kt - segTiles0) * 16; }
#pragma unroll
        for (int l = 0; l < 2; l++) {
            int s = tid + l * NTHR;
            int r = s >> 2, q = s & 3;
            ra[l] = *(const float4*)(A + (size_t)r * lda + kl + q * 4);
            rw[l] = *(const float4*)(W + (size_t)(n0 + r) * ldw + kl + q * 4);
        }
    };
    auto sts = [&](int st) {
        unsigned long long* A_ = sm + st * SSTAGE;
        unsigned long long* W_ = A_ + STILE;
#pragma unroll
        for (int l = 0; l < 2; l++) {
            int s = tid + l * NTHR;
            int r = s >> 2, q = s & 3;
            float va[4] = { ra[l].x, ra[l].y, ra[l].z, ra[l].w };
            float vw[4] = { rw[l].x, rw[l].y, rw[l].z, rw[l].w };
#pragma unroll
            for (int j = 0; j < 4; j++) {
                int p = kperm(q * 4 + j);
                A_[r * SROW + p] = pksplit(va[j]);
                W_[r * SROW + p] = pksplit(vw[j]);
            }
        }
    };

    float acc[4][4][4];
#pragma unroll
    for (int i = 0; i < 4; i++)
#pragma unroll
        for (int j = 0; j < 4; j++)
#pragma unroll
            for (int q = 0; q < 4; q++) acc[i][j][q] = 0.f;

    ldg(ktB);
    sts(0);
    __syncthreads();

    for (int kt = ktB; kt < ktE; kt++) {
        if (kt + 1 < ktE) ldg(kt + 1);
        const int st = (kt - ktB) & 1;
        const unsigned long long* A_ = sm + st * SSTAGE;
        const unsigned long long* W_ = A_ + STILE;
#pragma unroll
        for (int k8 = 0; k8 < 2; k8++) {
            const int kb = k8 * 8 + 2 * cc;
            uint4 B[4];
#pragma unroll
            for (int nf = 0; nf < 4; nf++) {
                int n = wn * 32 + nf * 8 + gid;
                B[nf] = *(const uint4*)&W_[n * SROW + kb];
            }
#pragma unroll
            for (int mf = 0; mf < 4; mf++) {
                int m = wm * 64 + mf * 16 + gid;
                uint4 va = *(const uint4*)&A_[m * SROW + kb];
                uint4 vb = *(const uint4*)&A_[(m + 8) * SROW + kb];
#pragma unroll
                for (int nf = 0; nf < 4; nf++) {
                    float* d = acc[mf][nf];
                    // (s0*s0) + (s0*s1) + (s1*s0) + (s1*s1)
                    mma_tf32(d[0], d[1], d[2], d[3],
                             va.x, vb.x, va.z, vb.z, B[nf].x, B[nf].z);
                    mma_tf32(d[0], d[1], d[2], d[3],
                             va.x, vb.x, va.z, vb.z, B[nf].y, B[nf].w);
                    mma_tf32(d[0], d[1], d[2], d[3],
                             va.y, vb.y, va.w, vb.w, B[nf].x, B[nf].z);
                    mma_tf32(d[0], d[1], d[2], d[3],
                             va.y, vb.y, va.w, vb.w, B[nf].y, B[nf].w);
                }
            }
        }
        if (kt + 1 < ktE) sts(st ^ 1);   // safe: all warps are past sync(kt-1)
        __syncthreads();
    }

#pragma unroll
    for (int mf = 0; mf < 4; mf++) {
        int m = wm * 64 + mf * 16 + gid;
#pragma unroll
        for (int nf = 0; nf < 4; nf++) {
            int col = n0 + wn * 32 + nf * 8 + 2 * cc;
            *(float2*)(Cp + (size_t)m * ldc + col) =
                make_float2(acc[mf][nf][0], acc[mf][nf][1]);
            *(float2*)(Cp + (size_t)(m + 8) * ldc + col) =
                make_float2(acc[mf][nf][2], acc[mf][nf][3]);
        }
    }
}

// ---------------- LSTM gate nonlinearity (sums 9 K-chunk partials) ----------------
__device__ void gate_phase(const float* __restrict__ bias,
                           float* __restrict__ h, float* __restrict__ c, int gtid)
{
    for (int idx = gtid; idx < Bsz * Hid; idx += GRIDB * NTHR) {
        int b = idx >> 10, j = idx & 1023;
        float gi = bias[j], gf = bias[1024 + j], gg = bias[2048 + j], go = bias[3072 + j];
        const float* pb = g_part + (size_t)b * G4;
#pragma unroll
        for (int ch = 0; ch < 9; ch++) {
            const float* q = pb + (size_t)ch * Bsz * G4;
            gi += q[j]; gf += q[1024 + j]; gg += q[2048 + j]; go += q[3072 + j];
        }
        float cc = sigm(gf) * c[idx] + sigm(gi) * tanhf(gg);
        c[idx] = cc;
        h[idx] = sigm(go) * tanhf(cc);
    }
}

// ---------------- params ----------------
struct Params {
    const int*   seq;
    const float* teacher_p;
    const float* embeds;
    const float* W_ih0; const float* W_hh0; const float* b_ih0; const float* b_hh0;
    const float* W_ih1; const float* W_hh1; const float* b_ih1; const float* b_hh1;
    const float* fc_w;  const float* fc_b;
    float* out;
};

// ---------------- the persistent kernel ----------------
__global__ void __launch_bounds__(NTHR, 2) lstm_persist(Params P)
{
    extern __shared__ unsigned long long smem_dyn[];
    __shared__ float red_v[NTHR];
    __shared__ int   red_i[NTHR];
    __shared__ int   s_tok;

    const int tid  = threadIdx.x;
    const int blk  = blockIdx.x;
    const int gtid = blk * NTHR + tid;
    unsigned long long lgen = g_gen;   // generation continuation across graph replays

    // ================= setup =================
    for (int idx = gtid; idx < Bsz * Hid; idx += GRIDB * NTHR) {
        g_H0[idx] = 0.f; g_C0[idx] = 0.f; g_H1[idx] = 0.f; g_C1[idx] = 0.f;
    }
    for (int i = gtid; i < G4; i += GRIDB * NTHR) {
        g_bias0[i] = P.b_ih0[i] + P.b_hh0[i];
        g_bias1[i] = P.b_ih1[i] + P.b_hh1[i];
    }
    if (blk < 128) {
        // threefry-2x32, partitionable scheme: bits[i] = o0 ^ o1,
        // (o0,o1) = threefry2x32(key=(0,1), (hi32(i)=0, lo32(i)=i))
        int j = blk * NTHR + tid;
        const unsigned ks0 = 0u, ks1 = 1u, ks2 = 0u ^ 1u ^ 0x1BD11BDAu;
#pragma unroll
        for (int half = 0; half < 2; half++) {
            unsigned idx = (unsigned)j + (unsigned)half * 32768u;
            unsigned x0 = 0u, x1 = idx;
            x0 += ks0; x1 += ks1;
#define R4(a,b,c,d) \
            x0 += x1; x1 = rotl32(x1,a); x1 ^= x0; \
            x0 += x1; x1 = rotl32(x1,b); x1 ^= x0; \
            x0 += x1; x1 = rotl32(x1,c); x1 ^= x0; \
            x0 += x1; x1 = rotl32(x1,d); x1 ^= x0;
            R4(13,15,26,6);   x0 += ks1; x1 += ks2 + 1u;
            R4(17,29,16,24);  x0 += ks2; x1 += ks0 + 2u;
            R4(13,15,26,6);   x0 += ks0; x1 += ks1 + 3u;
            R4(17,29,16,24);  x0 += ks1; x1 += ks2 + 4u;
            R4(13,15,26,6);   x0 += ks2; x1 += ks0 + 5u;
#undef R4
            unsigned bits = x0 ^ x1;
            float p = *P.teacher_p;
            float u = __uint_as_float((bits >> 9) | 0x3f800000u) - 1.0f;
            g_dec[idx] = (u < p) ? 1 : 0;
        }
        // embed for t = 0 (always teacher-forced)
        int b = blk;
        int tok = P.seq[b * Tlen];
        const float4* src = (const float4*)(P.embeds + (size_t)tok * Emb);
        float4* dst = (float4*)(g_X + (size_t)b * Emb);
        if (tid < 128)
            dst[tid] = (tok == 0) ? make_float4(0.f, 0.f, 0.f, 0.f) : src[tid];
    }
    grid_sync(lgen);

    // ================= time loop =================
    for (int t = 0; t < Tlen; t++) {
        // ---- layer 0: g = X @ W_ih0^T + H0 @ W_hh0^T (virtual K = 32|64 = 96 k-tiles)
        {
            int nt = blk % 32, chunk = blk / 32;   // 32 N-tiles(128) x 9 chunks
            int kb = chunk * 96 / 9, ke = (chunk + 1) * 96 / 9;
            mma_gemm(smem_dyn,
                     g_X, Emb, P.W_ih0, Emb, 32,
                     g_H0, Hid, P.W_hh0, Hid,
                     kb, ke, nt * 128,
                     g_part + (size_t)chunk * Bsz * G4, G4);
        }
        grid_sync(lgen);
        gate_phase(g_bias0, g_H0, g_C0, gtid);
        grid_sync(lgen);

        // ---- layer 1: g = H0 @ W_ih1^T + H1 @ W_hh1^T (virtual K = 64|64 = 128 k-tiles)
        {
            int nt = blk % 32, chunk = blk / 32;
            int kb = chunk * 128 / 9, ke = (chunk + 1) * 128 / 9;
            mma_gemm(smem_dyn,
                     g_H0, Hid, P.W_ih1, Hid, 64,
                     g_H1, Hid, P.W_hh1, Hid,
                     kb, ke, nt * 128,
                     g_part + (size_t)chunk * Bsz * G4, G4);
        }
        grid_sync(lgen);
        gate_phase(g_bias1, g_H1, g_C1, gtid);
        grid_sync(lgen);

        // ---- logits: H1 @ fc_w^T (K = 64 k-tiles; 4 N-tiles(128) x 16 chunks(4))
        if (blk < 64) {
            int nt = blk & 3, chunk = blk >> 2;
            mma_gemm(smem_dyn,
                     g_H1, Hid, P.fc_w, Hid, 64,
                     g_H1, Hid, P.fc_w, Hid,   // seg1 never reached
                     chunk * 4, chunk * 4 + 4, nt * 128,
                     g_lpart + (size_t)chunk * Bsz * Vocab, Vocab);
        }
        grid_sync(lgen);

        // ---- epilogue: sum 16 partials + bias, write out, argmax, next-token embed
        if (blk < 128) {
            int b = blk;
            float* orow = P.out + ((size_t)b * Tlen + t) * Vocab;
            float bv = -3.402823e38f; int bi = 0;
            for (int n = tid; n < Vocab; n += NTHR) {
                float v = P.fc_b[n];
#pragma unroll
                for (int ch = 0; ch < 16; ch++)
                    v += g_lpart[(size_t)ch * Bsz * Vocab + b * Vocab + n];
                orow[n] = v;
                if (v > bv) { bv = v; bi = n; }   // ascending n: strict > keeps first max
            }
            red_v[tid] = bv; red_i[tid] = bi;
            __syncthreads();
            for (int s = NTHR / 2; s > 0; s >>= 1) {
                if (tid < s) {
                    float v2 = red_v[tid + s]; int i2 = red_i[tid + s];
                    if (v2 > red_v[tid] || (v2 == red_v[tid] && i2 < red_i[tid])) {
                        red_v[tid] = v2; red_i[tid] = i2;
                    }
                }
                __syncthreads();
            }
            if (t + 1 < Tlen) {
                if (tid == 0) {
                    bool teacher = g_dec[(t + 1) * Bsz + b] != 0;
                    s_tok = teacher ? P.seq[b * Tlen + (t + 1)] : red_i[0];
                }
                __syncthreads();
                int tok = s_tok;
                const float4* src = (const float4*)(P.embeds + (size_t)tok * Emb);
                float4* dst = (float4*)(g_X + (size_t)b * Emb);
                if (tid < 128)
                    dst[tid] = (tok == 0) ? make_float4(0.f, 0.f, 0.f, 0.f) : src[tid];
            }
        }
        grid_sync(lgen);
    }
}

// ---------------- host launch: ONE kernel node, fully graph-capturable ----------------
extern "C" void kernel_launch(void* const* d_in, const int* in_sizes, int n_in,
                              void* d_out, int out_size)
{
    Params P;
    P.seq       = (const int*)d_in[0];
    // d_in[1] = seq_lens (unused by the reference computation)
    P.teacher_p = (const float*)d_in[2];
    P.embeds    = (const float*)d_in[3];
    P.W_ih0     = (const float*)d_in[4];
    P.W_hh0     = (const float*)d_in[5];
    P.b_ih0     = (const float*)d_in[6];
    P.b_hh0     = (const float*)d_in[7];
    P.W_ih1     = (const float*)d_in[8];
    P.W_hh1     = (const float*)d_in[9];
    P.b_ih1     = (const float*)d_in[10];
    P.b_hh1     = (const float*)d_in[11];
    P.fc_w      = (const float*)d_in[12];
    P.fc_b      = (const float*)d_in[13];
    P.out       = (float*)d_out;

    cudaFuncSetAttribute(lstm_persist, cudaFuncAttributeMaxDynamicSharedMemorySize,
                         SMEM_DYN);
    lstm_persist<<<GRIDB, NTHR, SMEM_DYN>>>(P);
}

// round 10
// speedup vs baseline: 1.0561x; 1.0561x over previous
#include <cuda_runtime.h>
#include <cstdint>
#include <cstddef>

#define GRIDB 288
#define NTHR  256
#define Bsz   128
#define Tlen  512
#define Vocab 512
#define Emb   512
#define Hid   1024
#define G4    4096

typedef unsigned long long u64t;

// smem: 2 stages x (sA 128x18 u64 + sW 128x18 u64)
#define SROW   18
#define KTU    2048                  // u64 per packed k-tile image (128 rows x 16 k)
#define STILE  (128 * SROW)
#define SSTAGE (2 * STILE)
#define SMEM_DYN (2 * SSTAGE * 8)    // 73728 bytes

// ---------------- device scratch (static; no runtime allocation) ----------------
// pre-split tf32-pair weight images: [tile][ktile][row*16 + kperm(k)]
__device__ u64t g_Wih0s[(size_t)32 * 32 * KTU];   // K=512,  N=4096
__device__ u64t g_Whh0s[(size_t)32 * 64 * KTU];   // K=1024, N=4096
__device__ u64t g_Wih1s[(size_t)32 * 64 * KTU];
__device__ u64t g_Whh1s[(size_t)32 * 64 * KTU];
__device__ u64t g_fcws [(size_t)4  * 64 * KTU];   // K=1024, N=512
// pre-split activation images: [ktile][row*16 + kperm(k)]
__device__ u64t g_Xi [(size_t)32 * KTU];
__device__ u64t g_H0i[(size_t)64 * KTU];
__device__ u64t g_H1i[(size_t)64 * KTU];

__device__ float g_C0[Bsz * Hid];
__device__ float g_C1[Bsz * Hid];
__device__ float g_part[9 * Bsz * G4];        // layer GEMM K-chunk partials
__device__ float g_lpart[64 * Bsz * Vocab];   // logits K-chunk partials (64 chunks)
__device__ float g_bias0[G4];
__device__ float g_bias1[G4];
__device__ unsigned char g_dec[Tlen * Bsz];

// ---------------- software grid barrier (generation-continued) ----------------
__device__ unsigned long long g_cnt;
__device__ volatile unsigned long long g_gen;

__device__ __forceinline__ void grid_sync(unsigned long long& lgen) {
    __threadfence();
    __syncthreads();
    if (threadIdx.x == 0) {
        lgen += 1ULL;
        unsigned long long a = atomicAdd(&g_cnt, 1ULL) + 1ULL;
        if (a == lgen * (unsigned long long)GRIDB) {
            g_gen = lgen;
            __threadfence();
        } else {
            while (g_gen < lgen) { __nanosleep(32); }
            __threadfence();
        }
    }
    __syncthreads();
}

// ---------------- small helpers ----------------
__device__ __forceinline__ unsigned rotl32(unsigned x, int d) {
    return (x << d) | (x >> (32 - d));
}
__device__ __forceinline__ float sigm(float x) { return 1.0f / (1.0f + expf(-x)); }

__device__ __forceinline__ uint32_t tf32c(float f) {
    uint32_t r;
    asm("cvt.rna.tf32.f32 %0, %1;" : "=r"(r) : "f"(f));
    return r;
}
// Dekker split: v = tf32(v) + tf32(residual) + O(2^-23 v)
__device__ __forceinline__ u64t pksplit(float v) {
    uint32_t u0 = tf32c(v);
    uint32_t u1 = tf32c(v - __uint_as_float(u0));
    return (u64t)u0 | ((u64t)u1 << 32);
}

__device__ __forceinline__ void mma_tf32(float& d0, float& d1, float& d2, float& d3,
                                         uint32_t a0, uint32_t a1, uint32_t a2, uint32_t a3,
                                         uint32_t b0, uint32_t b1) {
    asm volatile(
        "mma.sync.aligned.m16n8k8.row.col.f32.tf32.tf32.f32 "
        "{%0,%1,%2,%3}, {%4,%5,%6,%7}, {%8,%9}, {%0,%1,%2,%3};"
        : "+f"(d0), "+f"(d1), "+f"(d2), "+f"(d3)
        : "r"(a0), "r"(a1), "r"(a2), "r"(a3), "r"(b0), "r"(b1));
}

// k-permutation inside a 16-k tile: frag cols (c, c+4) become adjacent u64 pairs
__device__ __forceinline__ int kperm(int k) {
    return (k & 8) | ((k & 3) << 1) | ((k >> 2) & 1);
}

// ---------------- weight pre-split into packed image ----------------
__device__ void split_weight(const float* __restrict__ W, int N, int lgK,
                             u64t* __restrict__ img, int gtid) {
    const int K = 1 << lgK;
    const int KT = K >> 4;
    const int total = N << lgK;
    for (int e = gtid; e < total; e += GRIDB * NTHR) {
        int n = e >> lgK, k = e & (K - 1);
        int tile = n >> 7, row = n & 127;
        int kt = k >> 4, col = kperm(k & 15);
        img[((size_t)tile * KT + kt) * KTU + row * 16 + col] = pksplit(W[e]);
    }
}

// ---------------- tf32 3-term MMA GEMM reading pre-split images ----------------
// Output tile: 128 x 128 at column n0. Segmented virtual K of packed k-tile images.
__device__ void mma_gemm(u64t* sm,
    const u64t* __restrict__ A0, const u64t* __restrict__ W0, int seg0,
    const u64t* __restrict__ A1, const u64t* __restrict__ W1,
    int ktB, int ktE, float* __restrict__ Cp, int ldc, int n0)
{
    const int tid  = threadIdx.x;
    const int warp = tid >> 5, lane = tid & 31;
    const int wm = warp >> 2, wn = warp & 3;       // 2 x 4 warp grid, warp tile 64x32
    const int gid = lane >> 2, cc = lane & 3;

    uint4 ra[4], rw[4];

    auto ldg = [&](int kt) {
        const uint4* a4; const uint4* w4;
        if (kt < seg0) {
            a4 = (const uint4*)(A0 + (size_t)kt * KTU);
            w4 = (const uint4*)(W0 + (size_t)kt * KTU);
        } else {
            a4 = (const uint4*)(A1 + (size_t)(kt - seg0) * KTU);
            w4 = (const uint4*)(W1 + (size_t)(kt - seg0) * KTU);
        }
#pragma unroll
        for (int l = 0; l < 4; l++) {
            ra[l] = a4[tid + l * NTHR];
            rw[l] = w4[tid + l * NTHR];
        }
    };
    auto sts = [&](int st) {
        u64t* A_ = sm + st * SSTAGE;
        u64t* W_ = A_ + STILE;
#pragma unroll
        for (int l = 0; l < 4; l++) {
            int s = tid + l * NTHR;
            int row = s >> 3, c = (s & 7) * 2;
            *(uint4*)&A_[row * SROW + c] = ra[l];
            *(uint4*)&W_[row * SROW + c] = rw[l];
        }
    };

    float acc[4][4][4];
#pragma unroll
    for (int i = 0; i < 4; i++)
#pragma unroll
        for (int j = 0; j < 4; j++)
#pragma unroll
            for (int q = 0; q < 4; q++) acc[i][j][q] = 0.f;

    ldg(ktB);
    sts(0);
    __syncthreads();

    for (int kt = ktB; kt < ktE; kt++) {
        if (kt + 1 < ktE) ldg(kt + 1);
        const int st = (kt - ktB) & 1;
        const u64t* A_ = sm + st * SSTAGE;
        const u64t* W_ = A_ + STILE;
#pragma unroll
        for (int k8 = 0; k8 < 2; k8++) {
            const int kb = k8 * 8 + 2 * cc;
            uint4 B[4];
#pragma unroll
            for (int nf = 0; nf < 4; nf++) {
                int n = wn * 32 + nf * 8 + gid;
                B[nf] = *(const uint4*)&W_[n * SROW + kb];
            }
#pragma unroll
            for (int mf = 0; mf < 4; mf++) {
                int m = wm * 64 + mf * 16 + gid;
                uint4 va = *(const uint4*)&A_[m * SROW + kb];
                uint4 vb = *(const uint4*)&A_[(m + 8) * SROW + kb];
#pragma unroll
                for (int nf = 0; nf < 4; nf++) {
                    float* d = acc[mf][nf];
                    // 3-term: s0*s0 + s0*s1 + s1*s0 (drop s1*s1 ~ 2^-22)
                    mma_tf32(d[0], d[1], d[2], d[3],
                             va.x, vb.x, va.z, vb.z, B[nf].x, B[nf].z);
                    mma_tf32(d[0], d[1], d[2], d[3],
                             va.x, vb.x, va.z, vb.z, B[nf].y, B[nf].w);
                    mma_tf32(d[0], d[1], d[2], d[3],
                             va.y, vb.y, va.w, vb.w, B[nf].x, B[nf].z);
                }
            }
        }
        if (kt + 1 < ktE) sts(st ^ 1);   // safe: all warps passed sync(kt-1)
        __syncthreads();
    }

#pragma unroll
    for (int mf = 0; mf < 4; mf++) {
        int m = wm * 64 + mf * 16 + gid;
#pragma unroll
        for (int nf = 0; nf < 4; nf++) {
            int col = n0 + wn * 32 + nf * 8 + 2 * cc;
            *(float2*)(Cp + (size_t)m * ldc + col) =
                make_float2(acc[mf][nf][0], acc[mf][nf][1]);
            *(float2*)(Cp + (size_t)(m + 8) * ldc + col) =
                make_float2(acc[mf][nf][2], acc[mf][nf][3]);
        }
    }
}

// ---------------- LSTM gate: sums 9 partials, writes split image ----------------
__device__ void gate_phase(const float* __restrict__ bias, float* __restrict__ c,
                           u64t* __restrict__ himg, int gtid)
{
    for (int idx = gtid; idx < Bsz * Hid; idx += GRIDB * NTHR) {
        int b = idx >> 10, j = idx & 1023;
        float gi = bias[j], gf = bias[1024 + j], gg = bias[2048 + j], go = bias[3072 + j];
        const float* pb = g_part + (size_t)b * G4;
#pragma unroll
        for (int ch = 0; ch < 9; ch++) {
            const float* q = pb + (size_t)ch * Bsz * G4;
            gi += q[j]; gf += q[1024 + j]; gg += q[2048 + j]; go += q[3072 + j];
        }
        float ccv = sigm(gf) * c[idx] + sigm(gi) * tanhf(gg);
        c[idx] = ccv;
        float h = sigm(go) * tanhf(ccv);
        himg[(size_t)(j >> 4) * KTU + b * 16 + kperm(j & 15)] = pksplit(h);
    }
}

// ---------------- X image writer (token embed, split) ----------------
__device__ __forceinline__ void write_x(const float* __restrict__ embeds,
                                        int tok, int b, int tid)
{
    for (int col = tid; col < Emb; col += NTHR) {
        float v = (tok == 0) ? 0.f : embeds[(size_t)tok * Emb + col];
        g_Xi[(size_t)(col >> 4) * KTU + b * 16 + kperm(col & 15)] = pksplit(v);
    }
}

// ---------------- params ----------------
struct Params {
    const int*   seq;
    const float* teacher_p;
    const float* embeds;
    const float* W_ih0; const float* W_hh0; const float* b_ih0; const float* b_hh0;
    const float* W_ih1; const float* W_hh1; const float* b_ih1; const float* b_hh1;
    const float* fc_w;  const float* fc_b;
    float* out;
};

// ---------------- the persistent kernel ----------------
__global__ void __launch_bounds__(NTHR, 2) lstm_persist(Params P)
{
    extern __shared__ u64t smem_dyn[];
    __shared__ float red_v[NTHR];
    __shared__ int   red_i[NTHR];
    __shared__ int   s_tok;

    const int tid  = threadIdx.x;
    const int blk  = blockIdx.x;
    const int gtid = blk * NTHR + tid;
    unsigned long long lgen = g_gen;   // generation continuation across graph replays

    // ================= setup =================
    for (int idx = gtid; idx < Bsz * Hid; idx += GRIDB * NTHR) {
        g_C0[idx] = 0.f; g_C1[idx] = 0.f;
    }
    for (int idx = gtid; idx < 64 * KTU; idx += GRIDB * NTHR) {
        g_H0i[idx] = 0ULL; g_H1i[idx] = 0ULL;
    }
    for (int i = gtid; i < G4; i += GRIDB * NTHR) {
        g_bias0[i] = P.b_ih0[i] + P.b_hh0[i];
        g_bias1[i] = P.b_ih1[i] + P.b_hh1[i];
    }
    split_weight(P.W_ih0, G4,    9,  g_Wih0s, gtid);
    split_weight(P.W_hh0, G4,    10, g_Whh0s, gtid);
    split_weight(P.W_ih1, G4,    10, g_Wih1s, gtid);
    split_weight(P.W_hh1, G4,    10, g_Whh1s, gtid);
    split_weight(P.fc_w,  Vocab, 10, g_fcws,  gtid);

    if (blk < 128) {
        // threefry-2x32, partitionable scheme: bits[i] = o0 ^ o1,
        // (o0,o1) = threefry2x32(key=(0,1), (hi32(i)=0, lo32(i)=i))
        int j = blk * NTHR + tid;
        const unsigned ks0 = 0u, ks1 = 1u, ks2 = 0u ^ 1u ^ 0x1BD11BDAu;
#pragma unroll
        for (int half = 0; half < 2; half++) {
            unsigned idx = (unsigned)j + (unsigned)half * 32768u;
            unsigned x0 = 0u, x1 = idx;
            x0 += ks0; x1 += ks1;
#define R4(a,b,c,d) \
            x0 += x1; x1 = rotl32(x1,a); x1 ^= x0; \
            x0 += x1; x1 = rotl32(x1,b); x1 ^= x0; \
            x0 += x1; x1 = rotl32(x1,c); x1 ^= x0; \
            x0 += x1; x1 = rotl32(x1,d); x1 ^= x0;
            R4(13,15,26,6);   x0 += ks1; x1 += ks2 + 1u;
            R4(17,29,16,24);  x0 += ks2; x1 += ks0 + 2u;
            R4(13,15,26,6);   x0 += ks0; x1 += ks1 + 3u;
            R4(17,29,16,24);  x0 += ks1; x1 += ks2 + 4u;
            R4(13,15,26,6);   x0 += ks2; x1 += ks0 + 5u;
#undef R4
            unsigned bits = x0 ^ x1;
            float p = *P.teacher_p;
            float u = __uint_as_float((bits >> 9) | 0x3f800000u) - 1.0f;
            g_dec[idx] = (u < p) ? 1 : 0;
        }
        // X image for t = 0 (always teacher-forced)
        write_x(P.embeds, P.seq[blk * Tlen], blk, tid);
    }
    grid_sync(lgen);

    // ================= time loop =================
    for (int t = 0; t < Tlen; t++) {
        // ---- layer 0: X@Wih0 + H0@Whh0 (virtual K = 32|64 = 96 k-tiles)
        {
            int nt = blk % 32, chunk = blk / 32;   // 32 N-tiles x 9 chunks
            int kb = chunk * 96 / 9, ke = (chunk + 1) * 96 / 9;
            mma_gemm(smem_dyn,
                     g_Xi,  g_Wih0s + (size_t)nt * 32 * KTU, 32,
                     g_H0i, g_Whh0s + (size_t)nt * 64 * KTU,
                     kb, ke, g_part + (size_t)chunk * Bsz * G4, G4, nt * 128);
        }
        grid_sync(lgen);
        gate_phase(g_bias0, g_C0, g_H0i, gtid);
        grid_sync(lgen);

        // ---- layer 1: H0@Wih1 + H1@Whh1 (virtual K = 64|64 = 128 k-tiles)
        {
            int nt = blk % 32, chunk = blk / 32;
            int kb = chunk * 128 / 9, ke = (chunk + 1) * 128 / 9;
            mma_gemm(smem_dyn,
                     g_H0i, g_Wih1s + (size_t)nt * 64 * KTU, 64,
                     g_H1i, g_Whh1s + (size_t)nt * 64 * KTU,
                     kb, ke, g_part + (size_t)chunk * Bsz * G4, G4, nt * 128);
        }
        grid_sync(lgen);
        gate_phase(g_bias1, g_C1, g_H1i, gtid);
        grid_sync(lgen);

        // ---- logits: H1@fcw (64 k-tiles; 4 N-tiles x 64 chunks x 1 kt = 256 blocks)
        if (blk < 256) {
            int nt = blk & 3, chunk = blk >> 2;
            mma_gemm(smem_dyn,
                     g_H1i, g_fcws + (size_t)nt * 64 * KTU, 64,
                     g_H1i, g_fcws,    // seg1 never reached
                     chunk, chunk + 1, g_lpart + (size_t)chunk * Bsz * Vocab,
                     Vocab, nt * 128);
        }
        grid_sync(lgen);

        // ---- epilogue: sum 64 partials + bias, write out, argmax, next-token X image
        if (blk < 128) {
            int b = blk;
            float* orow = P.out + ((size_t)b * Tlen + t) * Vocab;
            float bv = -3.402823e38f; int bi = 0;
            for (int n = tid; n < Vocab; n += NTHR) {
                float v = P.fc_b[n];
#pragma unroll 8
                for (int ch = 0; ch < 64; ch++)
                    v += g_lpart[(size_t)ch * Bsz * Vocab + b * Vocab + n];
                orow[n] = v;
                if (v > bv) { bv = v; bi = n; }   // ascending n: strict > keeps first max
            }
            red_v[tid] = bv; red_i[tid] = bi;
            __syncthreads();
            for (int s = NTHR / 2; s > 0; s >>= 1) {
                if (tid < s) {
                    float v2 = red_v[tid + s]; int i2 = red_i[tid + s];
                    if (v2 > red_v[tid] || (v2 == red_v[tid] && i2 < red_i[tid])) {
                        red_v[tid] = v2; red_i[tid] = i2;
                    }
                }
                __syncthreads();
            }
            if (t + 1 < Tlen) {
                if (tid == 0) {
                    bool teacher = g_dec[(t + 1) * Bsz + b] != 0;
                    s_tok = teacher ? P.seq[b * Tlen + (t + 1)] : red_i[0];
                }
                __syncthreads();
                write_x(P.embeds, s_tok, b, tid);
            }
        }
        grid_sync(lgen);
    }
}

// ---------------- host launch: ONE kernel node, fully graph-capturable ----------------
extern "C" void kernel_launch(void* const* d_in, const int* in_sizes, int n_in,
                              void* d_out, int out_size)
{
    Params P;
    P.seq       = (const int*)d_in[0];
    // d_in[1] = seq_lens (unused by the reference computation)
    P.teacher_p = (const float*)d_in[2];
    P.embeds    = (const float*)d_in[3];
    P.W_ih0     = (const float*)d_in[4];
    P.W_hh0     = (const float*)d_in[5];
    P.b_ih0     = (const float*)d_in[6];
    P.b_hh0     = (const float*)d_in[7];
    P.W_ih1     = (const float*)d_in[8];
    P.W_hh1     = (const float*)d_in[9];
    P.b_ih1     = (const float*)d_in[10];
    P.b_hh1     = (const float*)d_in[11];
    P.fc_w      = (const float*)d_in[12];
    P.fc_b      = (const float*)d_in[13];
    P.out       = (float*)d_out;

    cudaFuncSetAttribute(lstm_persist, cudaFuncAttributeMaxDynamicSharedMemorySize,
                         SMEM_DYN);
    lstm_persist<<<GRIDB, NTHR, SMEM_DYN>>>(P);
}

// round 11
// speedup vs baseline: 1.8290x; 1.7318x over previous
#include <cuda_runtime.h>
#include <cstdint>
#include <cstddef>
#include <cuda_fp16.h>

#define GRIDB 288
#define NTHR  256
#define Bsz   128
#define Tlen  512
#define Vocab 512
#define Emb   512
#define Hid   1024
#define G4    4096

// packed fp16-pair images: one u32 per element = (s0 lo16, s1 hi16)
#define KTU    2048                  // u32 per k-tile image (128 rows x 16 k)
#define STG_U  (2 * KTU)             // A img + W img per stage (u32)
#define SMEM_DYN (2 * STG_U * 4)     // 2 stages = 32768 bytes

// ---------------- device scratch (static; no runtime allocation) ----------------
// weight images: [tile][ktile][row*16 + k] u32
__device__ uint32_t g_Wih0s[(size_t)32 * 32 * KTU];   // K=512,  N=4096  (8MB)
__device__ uint32_t g_Whh0s[(size_t)32 * 64 * KTU];   // K=1024, N=4096  (16MB)
__device__ uint32_t g_Wih1s[(size_t)32 * 64 * KTU];
__device__ uint32_t g_Whh1s[(size_t)32 * 64 * KTU];
__device__ uint32_t g_fcws [(size_t)4  * 64 * KTU];   // K=1024, N=512   (2MB)
// activation images: [ktile][row*16 + k]
__device__ uint32_t g_Xi [(size_t)32 * KTU];
__device__ uint32_t g_H0i[(size_t)64 * KTU];
__device__ uint32_t g_H1i[(size_t)64 * KTU];

__device__ float g_C0[Bsz * Hid];
__device__ float g_C1[Bsz * Hid];
__device__ float g_part[9 * Bsz * G4];        // layer GEMM K-chunk partials
__device__ float g_lpart[64 * Bsz * Vocab];   // logits K-chunk partials
__device__ float g_bias0[G4];
__device__ float g_bias1[G4];
__device__ unsigned char g_dec[Tlen * Bsz];

// ---------------- software grid barrier (generation-continued) ----------------
__device__ unsigned long long g_cnt;
__device__ volatile unsigned long long g_gen;

__device__ __forceinline__ void grid_sync(unsigned long long& lgen) {
    __threadfence();
    __syncthreads();
    if (threadIdx.x == 0) {
        lgen += 1ULL;
        unsigned long long a = atomicAdd(&g_cnt, 1ULL) + 1ULL;
        if (a == lgen * (unsigned long long)GRIDB) {
            g_gen = lgen;
            __threadfence();
        } else {
            while (g_gen < lgen) { __nanosleep(32); }
            __threadfence();
        }
    }
    __syncthreads();
}

// ---------------- small helpers ----------------
__device__ __forceinline__ unsigned rotl32(unsigned x, int d) {
    return (x << d) | (x >> (32 - d));
}
__device__ __forceinline__ float sigm(float x) { return 1.0f / (1.0f + expf(-x)); }

// fp16 2-split: v = s0 + s1 + r, |r| <= max(2^-22 |v|, 2^-25)
__device__ __forceinline__ uint32_t pksplit(float v) {
    __half h0 = __float2half_rn(v);
    __half h1 = __float2half_rn(v - __half2float(h0));
    return (uint32_t)__half_as_ushort(h0) | ((uint32_t)__half_as_ushort(h1) << 16);
}

__device__ __forceinline__ uint32_t prmt(uint32_t a, uint32_t b, uint32_t sel) {
    uint32_t d;
    asm("prmt.b32 %0, %1, %2, %3;" : "=r"(d) : "r"(a), "r"(b), "r"(sel));
    return d;
}

__device__ __forceinline__ void mma_f16(float& d0, float& d1, float& d2, float& d3,
                                        uint32_t a0, uint32_t a1, uint32_t a2, uint32_t a3,
                                        uint32_t b0, uint32_t b1) {
    asm volatile(
        "mma.sync.aligned.m16n8k16.row.col.f32.f16.f16.f32 "
        "{%0,%1,%2,%3}, {%4,%5,%6,%7}, {%8,%9}, {%0,%1,%2,%3};"
        : "+f"(d0), "+f"(d1), "+f"(d2), "+f"(d3)
        : "r"(a0), "r"(a1), "r"(a2), "r"(a3), "r"(b0), "r"(b1));
}

// ---------------- weight pre-split into packed image ----------------
__device__ void split_weight(const float* __restrict__ W, int N, int lgK,
                             uint32_t* __restrict__ img, int gtid) {
    const int K = 1 << lgK;
    const int KT = K >> 4;
    const int total = N << lgK;
    for (int e = gtid; e < total; e += GRIDB * NTHR) {
        int n = e >> lgK, k = e & (K - 1);
        img[((size_t)(n >> 7) * KT + (k >> 4)) * KTU + (n & 127) * 16 + (k & 15)]
            = pksplit(W[e]);
    }
}

// ---------------- fp16 3-term MMA GEMM reading packed images ----------------
// Output tile: 128 x 128 at column n0. Segmented virtual K of packed k16-tile images.
__device__ void mma_gemm(uint32_t* sm,
    const uint32_t* __restrict__ A0, const uint32_t* __restrict__ W0, int seg0,
    const uint32_t* __restrict__ A1, const uint32_t* __restrict__ W1,
    int ktB, int ktE, float* __restrict__ Cp, int ldc, int n0)
{
    const int tid  = threadIdx.x;
    const int warp = tid >> 5, lane = tid & 31;
    const int wm = warp >> 2, wn = warp & 3;       // 2 x 4 warp grid, warp tile 64x32
    const int gid = lane >> 2, cc = lane & 3;

    uint4 ra[2], rw[2];

    auto ldg = [&](int kt) {
        const uint4* a4; const uint4* w4;
        if (kt < seg0) {
            a4 = (const uint4*)(A0 + (size_t)kt * KTU);
            w4 = (const uint4*)(W0 + (size_t)kt * KTU);
        } else {
            a4 = (const uint4*)(A1 + (size_t)(kt - seg0) * KTU);
            w4 = (const uint4*)(W1 + (size_t)(kt - seg0) * KTU);
        }
#pragma unroll
        for (int l = 0; l < 2; l++) {              // 512 uint4 per image
            ra[l] = a4[tid + l * NTHR];
            rw[l] = w4[tid + l * NTHR];
        }
    };
    auto sts = [&](int st) {
        uint4* A_ = (uint4*)(sm + st * STG_U);
        uint4* W_ = (uint4*)(sm + st * STG_U + KTU);
#pragma unroll
        for (int l = 0; l < 2; l++) {
            A_[tid + l * NTHR] = ra[l];
            W_[tid + l * NTHR] = rw[l];
        }
    };

    float acc[4][4][4];
#pragma unroll
    for (int i = 0; i < 4; i++)
#pragma unroll
        for (int j = 0; j < 4; j++)
#pragma unroll
            for (int q = 0; q < 4; q++) acc[i][j][q] = 0.f;

    ldg(ktB);
    sts(0);
    __syncthreads();

    for (int kt = ktB; kt < ktE; kt++) {
        if (kt + 1 < ktE) ldg(kt + 1);
        const int st = (kt - ktB) & 1;
        const uint32_t* A_ = sm + st * STG_U;
        const uint32_t* W_ = A_ + KTU;

        // B fragments for all 4 nf (both splits)
        uint32_t bs0[4][2], bs1[4][2];
#pragma unroll
        for (int nf = 0; nf < 4; nf++) {
            int n = wn * 32 + nf * 8 + gid;
            uint2 e0 = *(const uint2*)&W_[n * 16 + 2 * cc];       // k = 2cc, 2cc+1
            uint2 e1 = *(const uint2*)&W_[n * 16 + 8 + 2 * cc];   // k = 8+2cc, +1
            bs0[nf][0] = prmt(e0.x, e0.y, 0x5410u);
            bs1[nf][0] = prmt(e0.x, e0.y, 0x7632u);
            bs0[nf][1] = prmt(e1.x, e1.y, 0x5410u);
            bs1[nf][1] = prmt(e1.x, e1.y, 0x7632u);
        }
#pragma unroll
        for (int mf = 0; mf < 4; mf++) {
            int m = wm * 64 + mf * 16 + gid;
            uint2 e00 = *(const uint2*)&A_[m * 16 + 2 * cc];
            uint2 e01 = *(const uint2*)&A_[m * 16 + 8 + 2 * cc];
            uint2 e10 = *(const uint2*)&A_[(m + 8) * 16 + 2 * cc];
            uint2 e11 = *(const uint2*)&A_[(m + 8) * 16 + 8 + 2 * cc];
            uint32_t as0_0 = prmt(e00.x, e00.y, 0x5410u);
            uint32_t as0_1 = prmt(e10.x, e10.y, 0x5410u);
            uint32_t as0_2 = prmt(e01.x, e01.y, 0x5410u);
            uint32_t as0_3 = prmt(e11.x, e11.y, 0x5410u);
            uint32_t as1_0 = prmt(e00.x, e00.y, 0x7632u);
            uint32_t as1_1 = prmt(e10.x, e10.y, 0x7632u);
            uint32_t as1_2 = prmt(e01.x, e01.y, 0x7632u);
            uint32_t as1_3 = prmt(e11.x, e11.y, 0x7632u);
#pragma unroll
            for (int nf = 0; nf < 4; nf++) {
                float* d = acc[mf][nf];
                // 3-term: s0*s0 + s0*s1 + s1*s0 (dropped s1*s1 ~ 2^-22)
                mma_f16(d[0], d[1], d[2], d[3],
                        as0_0, as0_1, as0_2, as0_3, bs0[nf][0], bs0[nf][1]);
                mma_f16(d[0], d[1], d[2], d[3],
                        as0_0, as0_1, as0_2, as0_3, bs1[nf][0], bs1[nf][1]);
                mma_f16(d[0], d[1], d[2], d[3],
                        as1_0, as1_1, as1_2, as1_3, bs0[nf][0], bs0[nf][1]);
            }
        }
        if (kt + 1 < ktE) sts(st ^ 1);   // safe: all warps passed sync(kt-1)
        __syncthreads();
    }

#pragma unroll
    for (int mf = 0; mf < 4; mf++) {
        int m = wm * 64 + mf * 16 + gid;
#pragma unroll
        for (int nf = 0; nf < 4; nf++) {
            int col = n0 + wn * 32 + nf * 8 + 2 * cc;
            *(float2*)(Cp + (size_t)m * ldc + col) =
                make_float2(acc[mf][nf][0], acc[mf][nf][1]);
            *(float2*)(Cp + (size_t)(m + 8) * ldc + col) =
                make_float2(acc[mf][nf][2], acc[mf][nf][3]);
        }
    }
}

// ---------------- LSTM gate: sums 9 partials, writes packed split image ----------
__device__ void gate_phase(const float* __restrict__ bias, float* __restrict__ c,
                           uint32_t* __restrict__ himg, int gtid)
{
    for (int idx = gtid; idx < Bsz * Hid; idx += GRIDB * NTHR) {
        int b = idx >> 10, j = idx & 1023;
        float gi = bias[j], gf = bias[1024 + j], gg = bias[2048 + j], go = bias[3072 + j];
        const float* pb = g_part + (size_t)b * G4;
#pragma unroll
        for (int ch = 0; ch < 9; ch++) {
            const float* q = pb + (size_t)ch * Bsz * G4;
            gi += q[j]; gf += q[1024 + j]; gg += q[2048 + j]; go += q[3072 + j];
        }
        float ccv = sigm(gf) * c[idx] + sigm(gi) * tanhf(gg);
        c[idx] = ccv;
        float h = sigm(go) * tanhf(ccv);
        himg[(size_t)(j >> 4) * KTU + b * 16 + (j & 15)] = pksplit(h);
    }
}

// ---------------- X image writer (token embed, split) ----------------
__device__ __forceinline__ void write_x(const float* __restrict__ embeds,
                                        int tok, int b, int tid)
{
    for (int col = tid; col < Emb; col += NTHR) {
        float v = (tok == 0) ? 0.f : embeds[(size_t)tok * Emb + col];
        g_Xi[(size_t)(col >> 4) * KTU + b * 16 + (col & 15)] = pksplit(v);
    }
}

// ---------------- params ----------------
struct Params {
    const int*   seq;
    const float* teacher_p;
    const float* embeds;
    const float* W_ih0; const float* W_hh0; const float* b_ih0; const float* b_hh0;
    const float* W_ih1; const float* W_hh1; const float* b_ih1; const float* b_hh1;
    const float* fc_w;  const float* fc_b;
    float* out;
};

// ---------------- the persistent kernel ----------------
__global__ void __launch_bounds__(NTHR, 2) lstm_persist(Params P)
{
    extern __shared__ uint32_t smem_dyn[];
    __shared__ float red_v[NTHR];
    __shared__ int   red_i[NTHR];
    __shared__ int   s_tok;

    const int tid  = threadIdx.x;
    const int blk  = blockIdx.x;
    const int gtid = blk * NTHR + tid;
    unsigned long long lgen = g_gen;   // generation continuation across graph replays

    // ================= setup =================
    for (int idx = gtid; idx < Bsz * Hid; idx += GRIDB * NTHR) {
        g_C0[idx] = 0.f; g_C1[idx] = 0.f;
    }
    for (int idx = gtid; idx < 64 * KTU; idx += GRIDB * NTHR) {
        g_H0i[idx] = 0u; g_H1i[idx] = 0u;
    }
    for (int i = gtid; i < G4; i += GRIDB * NTHR) {
        g_bias0[i] = P.b_ih0[i] + P.b_hh0[i];
        g_bias1[i] = P.b_ih1[i] + P.b_hh1[i];
    }
    split_weight(P.W_ih0, G4,    9,  g_Wih0s, gtid);
    split_weight(P.W_hh0, G4,    10, g_Whh0s, gtid);
    split_weight(P.W_ih1, G4,    10, g_Wih1s, gtid);
    split_weight(P.W_hh1, G4,    10, g_Whh1s, gtid);
    split_weight(P.fc_w,  Vocab, 10, g_fcws,  gtid);

    if (blk < 128) {
        // threefry-2x32, partitionable scheme: bits[i] = o0 ^ o1,
        // (o0,o1) = threefry2x32(key=(0,1), (hi32(i)=0, lo32(i)=i))
        int j = blk * NTHR + tid;
        const unsigned ks0 = 0u, ks1 = 1u, ks2 = 0u ^ 1u ^ 0x1BD11BDAu;
#pragma unroll
        for (int half = 0; half < 2; half++) {
            unsigned idx = (unsigned)j + (unsigned)half * 32768u;
            unsigned x0 = 0u, x1 = idx;
            x0 += ks0; x1 += ks1;
#define R4(a,b,c,d) \
            x0 += x1; x1 = rotl32(x1,a); x1 ^= x0; \
            x0 += x1; x1 = rotl32(x1,b); x1 ^= x0; \
            x0 += x1; x1 = rotl32(x1,c); x1 ^= x0; \
            x0 += x1; x1 = rotl32(x1,d); x1 ^= x0;
            R4(13,15,26,6);   x0 += ks1; x1 += ks2 + 1u;
            R4(17,29,16,24);  x0 += ks2; x1 += ks0 + 2u;
            R4(13,15,26,6);   x0 += ks0; x1 += ks1 + 3u;
            R4(17,29,16,24);  x0 += ks1; x1 += ks2 + 4u;
            R4(13,15,26,6);   x0 += ks2; x1 += ks0 + 5u;
#undef R4
            unsigned bits = x0 ^ x1;
            float p = *P.teacher_p;
            float u = __uint_as_float((bits >> 9) | 0x3f800000u) - 1.0f;
            g_dec[idx] = (u < p) ? 1 : 0;
        }
        // X image for t = 0 (always teacher-forced)
        write_x(P.embeds, P.seq[blk * Tlen], blk, tid);
    }
    grid_sync(lgen);

    // ================= time loop =================
    for (int t = 0; t < Tlen; t++) {
        // ---- layer 0: X@Wih0 + H0@Whh0 (virtual K = 32|64 = 96 k-tiles)
        {
            int nt = blk % 32, chunk = blk / 32;   // 32 N-tiles x 9 chunks
            int kb = chunk * 96 / 9, ke = (chunk + 1) * 96 / 9;
            mma_gemm(smem_dyn,
                     g_Xi,  g_Wih0s + (size_t)nt * 32 * KTU, 32,
                     g_H0i, g_Whh0s + (size_t)nt * 64 * KTU,
                     kb, ke, g_part + (size_t)chunk * Bsz * G4, G4, nt * 128);
        }
        grid_sync(lgen);
        gate_phase(g_bias0, g_C0, g_H0i, gtid);
        grid_sync(lgen);

        // ---- layer 1: H0@Wih1 + H1@Whh1 (virtual K = 64|64 = 128 k-tiles)
        {
            int nt = blk % 32, chunk = blk / 32;
            int kb = chunk * 128 / 9, ke = (chunk + 1) * 128 / 9;
            mma_gemm(smem_dyn,
                     g_H0i, g_Wih1s + (size_t)nt * 64 * KTU, 64,
                     g_H1i, g_Whh1s + (size_t)nt * 64 * KTU,
                     kb, ke, g_part + (size_t)chunk * Bsz * G4, G4, nt * 128);
        }
        grid_sync(lgen);
        gate_phase(g_bias1, g_C1, g_H1i, gtid);
        grid_sync(lgen);

        // ---- logits: H1@fcw (64 k-tiles; 4 N-tiles x 64 chunks x 1 kt = 256 blocks)
        if (blk < 256) {
            int nt = blk & 3, chunk = blk >> 2;
            mma_gemm(smem_dyn,
                     g_H1i, g_fcws + (size_t)nt * 64 * KTU, 64,
                     g_H1i, g_fcws,    // seg1 never reached
                     chunk, chunk + 1, g_lpart + (size_t)chunk * Bsz * Vocab,
                     Vocab, nt * 128);
        }
        grid_sync(lgen);

        // ---- epilogue: sum 64 partials + bias, write out, argmax, next-token X image
        if (blk < 128) {
            int b = blk;
            float* orow = P.out + ((size_t)b * Tlen + t) * Vocab;
            float bv = -3.402823e38f; int bi = 0;
            for (int n = tid; n < Vocab; n += NTHR) {
                float v = P.fc_b[n];
#pragma unroll 8
                for (int ch = 0; ch < 64; ch++)
                    v += g_lpart[(size_t)ch * Bsz * Vocab + b * Vocab + n];
                orow[n] = v;
                if (v > bv) { bv = v; bi = n; }   // ascending n: strict > keeps first max
            }
            red_v[tid] = bv; red_i[tid] = bi;
            __syncthreads();
            for (int s = NTHR / 2; s > 0; s >>= 1) {
                if (tid < s) {
                    float v2 = red_v[tid + s]; int i2 = red_i[tid + s];
                    if (v2 > red_v[tid] || (v2 == red_v[tid] && i2 < red_i[tid])) {
                        red_v[tid] = v2; red_i[tid] = i2;
                    }
                }
                __syncthreads();
            }
            if (t + 1 < Tlen) {
                if (tid == 0) {
                    bool teacher = g_dec[(t + 1) * Bsz + b] != 0;
                    s_tok = teacher ? P.seq[b * Tlen + (t + 1)] : red_i[0];
                }
                __syncthreads();
                write_x(P.embeds, s_tok, b, tid);
            }
        }
        grid_sync(lgen);
    }
}

// ---------------- host launch: ONE kernel node, fully graph-capturable ----------------
extern "C" void kernel_launch(void* const* d_in, const int* in_sizes, int n_in,
                              void* d_out, int out_size)
{
    Params P;
    P.seq       = (const int*)d_in[0];
    // d_in[1] = seq_lens (unused by the reference computation)
    P.teacher_p = (const float*)d_in[2];
    P.embeds    = (const float*)d_in[3];
    P.W_ih0     = (const float*)d_in[4];
    P.W_hh0     = (const float*)d_in[5];
    P.b_ih0     = (const float*)d_in[6];
    P.b_hh0     = (const float*)d_in[7];
    P.W_ih1     = (const float*)d_in[8];
    P.W_hh1     = (const float*)d_in[9];
    P.b_ih1     = (const float*)d_in[10];
    P.b_hh1     = (const float*)d_in[11];
    P.fc_w      = (const float*)d_in[12];
    P.fc_b      = (const float*)d_in[13];
    P.out       = (float*)d_out;

    cudaFuncSetAttribute(lstm_persist, cudaFuncAttributeMaxDynamicSharedMemorySize,
                         SMEM_DYN);
    lstm_persist<<<GRIDB, NTHR, SMEM_DYN>>>(P);
}

// round 12
// speedup vs baseline: 1.9631x; 1.0733x over previous
#include <cuda_runtime.h>
#include <cstdint>
#include <cstddef>
#include <cuda_fp16.h>

#define GRIDB 288
#define NTHR  256
#define Bsz   128
#define Tlen  512
#define Vocab 512
#define Emb   512
#define Hid   1024
#define G4    4096

// packed fp16-pair images: one u32 per element = (s0 lo16, s1 hi16)
#define KTU    2048                  // u32 per k-tile image (128 rows x 16 k)
#define NSTG   4                     // cp.async pipeline stages
#define STG_U  (2 * KTU)             // A img + W img per stage (u32)
#define SMEM_DYN (NSTG * STG_U * 4)  // 65536 bytes

#define LCH    32                    // logits partial chunks

// ---------------- device scratch (static; no runtime allocation) ----------------
__device__ uint32_t g_Wih0s[(size_t)32 * 32 * KTU];   // K=512,  N=4096  (8MB)
__device__ uint32_t g_Whh0s[(size_t)32 * 64 * KTU];   // K=1024, N=4096  (16MB)
__device__ uint32_t g_Wih1s[(size_t)32 * 64 * KTU];
__device__ uint32_t g_Whh1s[(size_t)32 * 64 * KTU];
__device__ uint32_t g_fcws [(size_t)4  * 64 * KTU];   // K=1024, N=512   (2MB)
__device__ uint32_t g_Xi [(size_t)32 * KTU];
__device__ uint32_t g_H0i[(size_t)64 * KTU];
__device__ uint32_t g_H1i[(size_t)64 * KTU];

__device__ float g_C0[Bsz * Hid];
__device__ float g_C1[Bsz * Hid];
__device__ float g_part[9 * Bsz * G4];          // layer GEMM K-chunk partials
__device__ float g_lpart[LCH * Bsz * Vocab];    // logits K-chunk partials
__device__ float g_bias0[G4];
__device__ float g_bias1[G4];
__device__ unsigned char g_dec[Tlen * Bsz];

// ---------------- software grid barrier (generation-continued) ----------------
__device__ unsigned long long g_cnt;
__device__ volatile unsigned long long g_gen;

__device__ __forceinline__ void grid_sync(unsigned long long& lgen) {
    __threadfence();
    __syncthreads();
    if (threadIdx.x == 0) {
        lgen += 1ULL;
        unsigned long long a = atomicAdd(&g_cnt, 1ULL) + 1ULL;
        if (a == lgen * (unsigned long long)GRIDB) {
            g_gen = lgen;
            __threadfence();
        } else {
            while (g_gen < lgen) { __nanosleep(16); }
            __threadfence();
        }
    }
    __syncthreads();
}

// ---------------- small helpers ----------------
__device__ __forceinline__ unsigned rotl32(unsigned x, int d) {
    return (x << d) | (x >> (32 - d));
}
__device__ __forceinline__ float sigm(float x) { return 1.0f / (1.0f + expf(-x)); }

// fp16 2-split: v = s0 + s1 + r, |r| <= max(2^-22 |v|, 2^-25)
__device__ __forceinline__ uint32_t pksplit(float v) {
    __half h0 = __float2half_rn(v);
    __half h1 = __float2half_rn(v - __half2float(h0));
    return (uint32_t)__half_as_ushort(h0) | ((uint32_t)__half_as_ushort(h1) << 16);
}

__device__ __forceinline__ uint32_t prmt(uint32_t a, uint32_t b, uint32_t sel) {
    uint32_t d;
    asm("prmt.b32 %0, %1, %2, %3;" : "=r"(d) : "r"(a), "r"(b), "r"(sel));
    return d;
}

__device__ __forceinline__ void mma_f16(float& d0, float& d1, float& d2, float& d3,
                                        uint32_t a0, uint32_t a1, uint32_t a2, uint32_t a3,
                                        uint32_t b0, uint32_t b1) {
    asm volatile(
        "mma.sync.aligned.m16n8k16.row.col.f32.f16.f16.f32 "
        "{%0,%1,%2,%3}, {%4,%5,%6,%7}, {%8,%9}, {%0,%1,%2,%3};"
        : "+f"(d0), "+f"(d1), "+f"(d2), "+f"(d3)
        : "r"(a0), "r"(a1), "r"(a2), "r"(a3), "r"(b0), "r"(b1));
}

__device__ __forceinline__ void cpa16(uint32_t s, const void* g) {
    asm volatile("cp.async.cg.shared.global [%0], [%1], 16;" :: "r"(s), "l"(g));
}
#define CP_COMMIT() asm volatile("cp.async.commit_group;" ::: "memory")
#define CP_WAIT2()  asm volatile("cp.async.wait_group 2;" ::: "memory")

// ---------------- weight pre-split into packed image ----------------
__device__ void split_weight(const float* __restrict__ W, int N, int lgK,
                             uint32_t* __restrict__ img, int gtid) {
    const int K = 1 << lgK;
    const int KT = K >> 4;
    const int total = N << lgK;
    for (int e = gtid; e < total; e += GRIDB * NTHR) {
        int n = e >> lgK, k = e & (K - 1);
        img[((size_t)(n >> 7) * KT + (k >> 4)) * KTU + (n & 127) * 16 + (k & 15)]
            = pksplit(W[e]);
    }
}

// ---------------- fp16 3-term MMA GEMM, 4-stage cp.async pipeline ----------------
// Output tile: 128 x 128 at column n0. Segmented virtual K of packed k16-tile images.
__device__ void mma_gemm(uint32_t* sm,
    const uint32_t* __restrict__ A0, const uint32_t* __restrict__ W0, int seg0,
    const uint32_t* __restrict__ A1, const uint32_t* __restrict__ W1,
    int ktB, int ktE, float* __restrict__ Cp, int ldc, int n0)
{
    const int tid  = threadIdx.x;
    const int warp = tid >> 5, lane = tid & 31;
    const int wm = warp >> 2, wn = warp & 3;       // 2 x 4 warp grid, warp tile 64x32
    const int gid = lane >> 2, cc = lane & 3;
    const uint32_t sbase = (uint32_t)__cvta_generic_to_shared(sm);

    auto issue = [&](int kt, int stage) {
        const uint4* a4; const uint4* w4;
        if (kt < seg0) {
            a4 = (const uint4*)(A0 + (size_t)kt * KTU);
            w4 = (const uint4*)(W0 + (size_t)kt * KTU);
        } else {
            a4 = (const uint4*)(A1 + (size_t)(kt - seg0) * KTU);
            w4 = (const uint4*)(W1 + (size_t)(kt - seg0) * KTU);
        }
        uint32_t sa = sbase + stage * (STG_U * 4);
        uint32_t sw = sa + KTU * 4;
#pragma unroll
        for (int l = 0; l < 2; l++) {
            int s = tid + l * NTHR;                // 512 uint4 per image
            cpa16(sa + s * 16, a4 + s);
            cpa16(sw + s * 16, w4 + s);
        }
    };

    float acc[4][4][4];
#pragma unroll
    for (int i = 0; i < 4; i++)
#pragma unroll
        for (int j = 0; j < 4; j++)
#pragma unroll
            for (int q = 0; q < 4; q++) acc[i][j][q] = 0.f;

    const int nkt = ktE - ktB;
#pragma unroll
    for (int s = 0; s < NSTG - 1; s++) {
        if (s < nkt) issue(ktB + s, s);
        CP_COMMIT();
    }

    for (int kt = ktB; kt < ktE; kt++) {
        CP_WAIT2();
        __syncthreads();                           // stage (kt) visible to all warps
        const int st = (kt - ktB) & (NSTG - 1);
        // refill stage that was computed at kt-1 (all warps are past top-sync)
        if (kt + NSTG - 1 < ktE) issue(kt + NSTG - 1, (kt - ktB + NSTG - 1) & (NSTG - 1));
        CP_COMMIT();

        const uint32_t* A_ = sm + st * STG_U;
        const uint32_t* W_ = A_ + KTU;

        uint32_t bs0[4][2], bs1[4][2];
#pragma unroll
        for (int nf = 0; nf < 4; nf++) {
            int n = wn * 32 + nf * 8 + gid;
            uint2 e0 = *(const uint2*)&W_[n * 16 + 2 * cc];
            uint2 e1 = *(const uint2*)&W_[n * 16 + 8 + 2 * cc];
            bs0[nf][0] = prmt(e0.x, e0.y, 0x5410u);
            bs1[nf][0] = prmt(e0.x, e0.y, 0x7632u);
            bs0[nf][1] = prmt(e1.x, e1.y, 0x5410u);
            bs1[nf][1] = prmt(e1.x, e1.y, 0x7632u);
        }
#pragma unroll
        for (int mf = 0; mf < 4; mf++) {
            int m = wm * 64 + mf * 16 + gid;
            uint2 e00 = *(const uint2*)&A_[m * 16 + 2 * cc];
            uint2 e01 = *(const uint2*)&A_[m * 16 + 8 + 2 * cc];
            uint2 e10 = *(const uint2*)&A_[(m + 8) * 16 + 2 * cc];
            uint2 e11 = *(const uint2*)&A_[(m + 8) * 16 + 8 + 2 * cc];
            uint32_t as0_0 = prmt(e00.x, e00.y, 0x5410u);
            uint32_t as0_1 = prmt(e10.x, e10.y, 0x5410u);
            uint32_t as0_2 = prmt(e01.x, e01.y, 0x5410u);
            uint32_t as0_3 = prmt(e11.x, e11.y, 0x5410u);
            uint32_t as1_0 = prmt(e00.x, e00.y, 0x7632u);
            uint32_t as1_1 = prmt(e10.x, e10.y, 0x7632u);
            uint32_t as1_2 = prmt(e01.x, e01.y, 0x7632u);
            uint32_t as1_3 = prmt(e11.x, e11.y, 0x7632u);
#pragma unroll
            for (int nf = 0; nf < 4; nf++) {
                float* d = acc[mf][nf];
                // 3-term: s0*s0 + s0*s1 + s1*s0 (dropped s1*s1 ~ 2^-22)
                mma_f16(d[0], d[1], d[2], d[3],
                        as0_0, as0_1, as0_2, as0_3, bs0[nf][0], bs0[nf][1]);
                mma_f16(d[0], d[1], d[2], d[3],
                        as0_0, as0_1, as0_2, as0_3, bs1[nf][0], bs1[nf][1]);
                mma_f16(d[0], d[1], d[2], d[3],
                        as1_0, as1_1, as1_2, as1_3, bs0[nf][0], bs0[nf][1]);
            }
        }
        __syncthreads();                           // all reads of stage done before refill next iter
    }

#pragma unroll
    for (int mf = 0; mf < 4; mf++) {
        int m = wm * 64 + mf * 16 + gid;
#pragma unroll
        for (int nf = 0; nf < 4; nf++) {
            int col = n0 + wn * 32 + nf * 8 + 2 * cc;
            *(float2*)(Cp + (size_t)m * ldc + col) =
                make_float2(acc[mf][nf][0], acc[mf][nf][1]);
            *(float2*)(Cp + (size_t)(m + 8) * ldc + col) =
                make_float2(acc[mf][nf][2], acc[mf][nf][3]);
        }
    }
}

// ---------------- LSTM gate: vectorized (4 j per thread) ----------------
__device__ void gate_phase(const float* __restrict__ bias, float* __restrict__ c,
                           uint32_t* __restrict__ himg, int gtid)
{
    for (int g = gtid; g < (Bsz * Hid) / 4; g += GRIDB * NTHR) {
        int idx = g * 4;
        int b = idx >> 10, j = idx & 1023;         // j multiple of 4
        float4 gi = *(const float4*)&bias[j];
        float4 gf = *(const float4*)&bias[1024 + j];
        float4 gg = *(const float4*)&bias[2048 + j];
        float4 go = *(const float4*)&bias[3072 + j];
        const float* pb = g_part + (size_t)b * G4;
#pragma unroll
        for (int ch = 0; ch < 9; ch++) {
            const float* q = pb + (size_t)ch * Bsz * G4;
            float4 a = *(const float4*)&q[j];
            float4 f = *(const float4*)&q[1024 + j];
            float4 gv = *(const float4*)&q[2048 + j];
            float4 o = *(const float4*)&q[3072 + j];
            gi.x += a.x; gi.y += a.y; gi.z += a.z; gi.w += a.w;
            gf.x += f.x; gf.y += f.y; gf.z += f.z; gf.w += f.w;
            gg.x += gv.x; gg.y += gv.y; gg.z += gv.z; gg.w += gv.w;
            go.x += o.x; go.y += o.y; go.z += o.z; go.w += o.w;
        }
        float4 cv = *(const float4*)&c[idx];
        float4 hv;
        cv.x = sigm(gf.x) * cv.x + sigm(gi.x) * tanhf(gg.x);
        cv.y = sigm(gf.y) * cv.y + sigm(gi.y) * tanhf(gg.y);
        cv.z = sigm(gf.z) * cv.z + sigm(gi.z) * tanhf(gg.z);
        cv.w = sigm(gf.w) * cv.w + sigm(gi.w) * tanhf(gg.w);
        hv.x = sigm(go.x) * tanhf(cv.x);
        hv.y = sigm(go.y) * tanhf(cv.y);
        hv.z = sigm(go.z) * tanhf(cv.z);
        hv.w = sigm(go.w) * tanhf(cv.w);
        *(float4*)&c[idx] = cv;
        uint4 pk = make_uint4(pksplit(hv.x), pksplit(hv.y), pksplit(hv.z), pksplit(hv.w));
        *(uint4*)&himg[(size_t)(j >> 4) * KTU + b * 16 + (j & 15)] = pk;
    }
}

// ---------------- X image writer (token embed, split) ----------------
__device__ __forceinline__ void write_x(const float* __restrict__ embeds,
                                        int tok, int b, int tid)
{
    for (int col = tid; col < Emb; col += NTHR) {
        float v = (tok == 0) ? 0.f : embeds[(size_t)tok * Emb + col];
        g_Xi[(size_t)(col >> 4) * KTU + b * 16 + (col & 15)] = pksplit(v);
    }
}

// ---------------- params ----------------
struct Params {
    const int*   seq;
    const float* teacher_p;
    const float* embeds;
    const float* W_ih0; const float* W_hh0; const float* b_ih0; const float* b_hh0;
    const float* W_ih1; const float* W_hh1; const float* b_ih1; const float* b_hh1;
    const float* fc_w;  const float* fc_b;
    float* out;
};

// ---------------- the persistent kernel ----------------
__global__ void __launch_bounds__(NTHR, 2) lstm_persist(Params P)
{
    extern __shared__ uint32_t smem_dyn[];
    __shared__ float red_v[NTHR];
    __shared__ int   red_i[NTHR];
    __shared__ int   s_tok;

    const int tid  = threadIdx.x;
    const int blk  = blockIdx.x;
    const int gtid = blk * NTHR + tid;
    unsigned long long lgen = g_gen;   // generation continuation across graph replays

    // ================= setup =================
    for (int idx = gtid; idx < Bsz * Hid; idx += GRIDB * NTHR) {
        g_C0[idx] = 0.f; g_C1[idx] = 0.f;
    }
    for (int idx = gtid; idx < 64 * KTU; idx += GRIDB * NTHR) {
        g_H0i[idx] = 0u; g_H1i[idx] = 0u;
    }
    for (int i = gtid; i < G4; i += GRIDB * NTHR) {
        g_bias0[i] = P.b_ih0[i] + P.b_hh0[i];
        g_bias1[i] = P.b_ih1[i] + P.b_hh1[i];
    }
    split_weight(P.W_ih0, G4,    9,  g_Wih0s, gtid);
    split_weight(P.W_hh0, G4,    10, g_Whh0s, gtid);
    split_weight(P.W_ih1, G4,    10, g_Wih1s, gtid);
    split_weight(P.W_hh1, G4,    10, g_Whh1s, gtid);
    split_weight(P.fc_w,  Vocab, 10, g_fcws,  gtid);

    if (blk < 128) {
        // threefry-2x32, partitionable scheme: bits[i] = o0 ^ o1,
        // (o0,o1) = threefry2x32(key=(0,1), (hi32(i)=0, lo32(i)=i))
        int j = blk * NTHR + tid;
        const unsigned ks0 = 0u, ks1 = 1u, ks2 = 0u ^ 1u ^ 0x1BD11BDAu;
#pragma unroll
        for (int half = 0; half < 2; half++) {
            unsigned idx = (unsigned)j + (unsigned)half * 32768u;
            unsigned x0 = 0u, x1 = idx;
            x0 += ks0; x1 += ks1;
#define R4(a,b,c,d) \
            x0 += x1; x1 = rotl32(x1,a); x1 ^= x0; \
            x0 += x1; x1 = rotl32(x1,b); x1 ^= x0; \
            x0 += x1; x1 = rotl32(x1,c); x1 ^= x0; \
            x0 += x1; x1 = rotl32(x1,d); x1 ^= x0;
            R4(13,15,26,6);   x0 += ks1; x1 += ks2 + 1u;
            R4(17,29,16,24);  x0 += ks2; x1 += ks0 + 2u;
            R4(13,15,26,6);   x0 += ks0; x1 += ks1 + 3u;
            R4(17,29,16,24);  x0 += ks1; x1 += ks2 + 4u;
            R4(13,15,26,6);   x0 += ks2; x1 += ks0 + 5u;
#undef R4
            unsigned bits = x0 ^ x1;
            float p = *P.teacher_p;
            float u = __uint_as_float((bits >> 9) | 0x3f800000u) - 1.0f;
            g_dec[idx] = (u < p) ? 1 : 0;
        }
        // X image for t = 0 (always teacher-forced)
        write_x(P.embeds, P.seq[blk * Tlen], blk, tid);
    }
    grid_sync(lgen);

    // ================= time loop =================
    for (int t = 0; t < Tlen; t++) {
        // ---- layer 0: X@Wih0 + H0@Whh0 (virtual K = 32|64 = 96 k-tiles)
        {
            int nt = blk % 32, chunk = blk / 32;   // 32 N-tiles x 9 chunks
            int kb = chunk * 96 / 9, ke = (chunk + 1) * 96 / 9;
            mma_gemm(smem_dyn,
                     g_Xi,  g_Wih0s + (size_t)nt * 32 * KTU, 32,
                     g_H0i, g_Whh0s + (size_t)nt * 64 * KTU,
                     kb, ke, g_part + (size_t)chunk * Bsz * G4, G4, nt * 128);
        }
        grid_sync(lgen);
        gate_phase(g_bias0, g_C0, g_H0i, gtid);
        grid_sync(lgen);

        // ---- layer 1: H0@Wih1 + H1@Whh1 (virtual K = 64|64 = 128 k-tiles)
        {
            int nt = blk % 32, chunk = blk / 32;
            int kb = chunk * 128 / 9, ke = (chunk + 1) * 128 / 9;
            mma_gemm(smem_dyn,
                     g_H0i, g_Wih1s + (size_t)nt * 64 * KTU, 64,
                     g_H1i, g_Whh1s + (size_t)nt * 64 * KTU,
                     kb, ke, g_part + (size_t)chunk * Bsz * G4, G4, nt * 128);
        }
        grid_sync(lgen);
        gate_phase(g_bias1, g_C1, g_H1i, gtid);
        grid_sync(lgen);

        // ---- logits: H1@fcw (64 k-tiles; 4 N-tiles x 32 chunks x 2 kt = 128 blocks)
        if (blk < 128) {
            int nt = blk & 3, chunk = blk >> 2;
            mma_gemm(smem_dyn,
                     g_H1i, g_fcws + (size_t)nt * 64 * KTU, 64,
                     g_H1i, g_fcws,    // seg1 never reached
                     chunk * 2, chunk * 2 + 2, g_lpart + (size_t)chunk * Bsz * Vocab,
                     Vocab, nt * 128);
        }
        grid_sync(lgen);

        // ---- epilogue: sum LCH partials + bias (float4), write out, argmax, next X
        if (blk < 128) {
            int b = blk;
            float* orow = P.out + ((size_t)b * Tlen + t) * Vocab;
            float bv = -3.402823e38f; int bi = 0;
            for (int n4 = tid; n4 < Vocab / 4; n4 += NTHR) {
                int n = n4 * 4;
                float4 v = *(const float4*)&P.fc_b[n];
#pragma unroll 8
                for (int ch = 0; ch < LCH; ch++) {
                    const float4 p4 = *(const float4*)
                        &g_lpart[(size_t)ch * Bsz * Vocab + b * Vocab + n];
                    v.x += p4.x; v.y += p4.y; v.z += p4.z; v.w += p4.w;
                }
                *(float4*)&orow[n] = v;
                if (v.x > bv) { bv = v.x; bi = n; }
                if (v.y > bv) { bv = v.y; bi = n + 1; }
                if (v.z > bv) { bv = v.z; bi = n + 2; }
                if (v.w > bv) { bv = v.w; bi = n + 3; }
            }
            red_v[tid] = bv; red_i[tid] = bi;
            __syncthreads();
            for (int s = NTHR / 2; s > 0; s >>= 1) {
                if (tid < s) {
                    float v2 = red_v[tid + s]; int i2 = red_i[tid + s];
                    if (v2 > red_v[tid] || (v2 == red_v[tid] && i2 < red_i[tid])) {
                        red_v[tid] = v2; red_i[tid] = i2;
                    }
                }
                __syncthreads();
            }
            if (t + 1 < Tlen) {
                if (tid == 0) {
                    bool teacher = g_dec[(t + 1) * Bsz + b] != 0;
                    s_tok = teacher ? P.seq[b * Tlen + (t + 1)] : red_i[0];
                }
                __syncthreads();
                write_x(P.embeds, s_tok, b, tid);
            }
        }
        grid_sync(lgen);
    }
}

// ---------------- host launch: ONE kernel node, fully graph-capturable ----------------
extern "C" void kernel_launch(void* const* d_in, const int* in_sizes, int n_in,
                              void* d_out, int out_size)
{
    Params P;
    P.seq       = (const int*)d_in[0];
    // d_in[1] = seq_lens (unused by the reference computation)
    P.teacher_p = (const float*)d_in[2];
    P.embeds    = (const float*)d_in[3];
    P.W_ih0     = (const float*)d_in[4];
    P.W_hh0     = (const float*)d_in[5];
    P.b_ih0     = (const float*)d_in[6];
    P.b_hh0     = (const float*)d_in[7];
    P.W_ih1     = (const float*)d_in[8];
    P.W_hh1     = (const float*)d_in[9];
    P.b_ih1     = (const float*)d_in[10];
    P.b_hh1     = (const float*)d_in[11];
    P.fc_w      = (const float*)d_in[12];
    P.fc_b      = (const float*)d_in[13];
    P.out       = (float*)d_out;

    cudaFuncSetAttribute(lstm_persist, cudaFuncAttributeMaxDynamicSharedMemorySize,
                         SMEM_DYN);
    lstm_persist<<<GRIDB, NTHR, SMEM_DYN>>>(P);
}

// round 14
// speedup vs baseline: 2.1608x; 1.1007x over previous
#include <cuda_runtime.h>
#include <cstdint>
#include <cstddef>
#include <cuda_fp16.h>

#define GRIDB 288
#define NTHR  256
#define Bsz   128
#define Tlen  512
#define Vocab 512
#define Emb   512
#define Hid   1024
#define G4    4096

// planar fp16-pair images: per k-tile = plane0 (128x16 u16 s0) + plane1 (s1), 8KB
// row-swizzle: u32-unit u of row r stored at physical unit u ^ (((r>>2)&1)<<2)
#define KTU    2048                  // u32 per k-tile image (2 planes x 1024)
#define NSTG   4                     // cp.async pipeline stages
#define STG_U  (2 * KTU)             // A img + W img per stage (u32)
#define SMEM_DYN (NSTG * STG_U * 4)  // 65536 bytes

#define LCH    32                    // logits partial chunks

// ---------------- device scratch (static; no runtime allocation) ----------------
__device__ uint32_t g_Wih0s[(size_t)32 * 32 * KTU];   // K=512,  N=4096  (8MB)
__device__ uint32_t g_Whh0s[(size_t)32 * 64 * KTU];   // K=1024, N=4096  (16MB)
__device__ uint32_t g_Wih1s[(size_t)32 * 64 * KTU];
__device__ uint32_t g_Whh1s[(size_t)32 * 64 * KTU];
__device__ uint32_t g_fcws [(size_t)4  * 64 * KTU];   // K=1024, N=512   (2MB)
__device__ uint32_t g_Xi [(size_t)32 * KTU];
__device__ uint32_t g_H0i[(size_t)64 * KTU];
__device__ uint32_t g_H1i[(size_t)64 * KTU];

__device__ float g_C0[Bsz * Hid];
__device__ float g_C1[Bsz * Hid];
__device__ float g_part[9 * Bsz * G4];          // layer GEMM K-chunk partials
__device__ float g_lpart[LCH * Bsz * Vocab];    // logits K-chunk partials
__device__ float g_bias0[G4];
__device__ float g_bias1[G4];
__device__ unsigned char g_dec[Tlen * Bsz];

// ---------------- software grid barrier (generation-continued) ----------------
__device__ unsigned long long g_cnt;
__device__ volatile unsigned long long g_gen;

__device__ __forceinline__ void grid_sync(unsigned long long& lgen) {
    __threadfence();
    __syncthreads();
    if (threadIdx.x == 0) {
        lgen += 1ULL;
        unsigned long long a = atomicAdd(&g_cnt, 1ULL) + 1ULL;
        if (a == lgen * (unsigned long long)GRIDB) {
            g_gen = lgen;
            __threadfence();
        } else {
            while (g_gen < lgen) { __nanosleep(16); }
            __threadfence();
        }
    }
    __syncthreads();
}

// ---------------- small helpers ----------------
__device__ __forceinline__ unsigned rotl32(unsigned x, int d) {
    return (x << d) | (x >> (32 - d));
}
// fast sigmoid / tanh: __expf + __fdividef, rel err ~1e-7 (vs 1e-3 threshold)
__device__ __forceinline__ float fsigm(float x) {
    return __fdividef(1.0f, 1.0f + __expf(-x));
}
__device__ __forceinline__ float ftanh(float x) {
    return __fdividef(2.0f, 1.0f + __expf(-2.0f * x)) - 1.0f;
}

__device__ __forceinline__ unsigned short h0u(float v) {
    return __half_as_ushort(__float2half_rn(v));
}
__device__ __forceinline__ unsigned short h1u(float v) {
    float r = v - __half2float(__float2half_rn(v));
    return __half_as_ushort(__float2half_rn(r));
}

__device__ __forceinline__ void mma_f16(float& d0, float& d1, float& d2, float& d3,
                                        uint32_t a0, uint32_t a1, uint32_t a2, uint32_t a3,
                                        uint32_t b0, uint32_t b1) {
    asm volatile(
        "mma.sync.aligned.m16n8k16.row.col.f32.f16.f16.f32 "
        "{%0,%1,%2,%3}, {%4,%5,%6,%7}, {%8,%9}, {%0,%1,%2,%3};"
        : "+f"(d0), "+f"(d1), "+f"(d2), "+f"(d3)
        : "r"(a0), "r"(a1), "r"(a2), "r"(a3), "r"(b0), "r"(b1));
}

__device__ __forceinline__ void cpa16(uint32_t s, const void* g) {
    asm volatile("cp.async.cg.shared.global [%0], [%1], 16;" :: "r"(s), "l"(g));
}
#define CP_COMMIT() asm volatile("cp.async.commit_group;" ::: "memory")
#define CP_WAIT2()  asm volatile("cp.async.wait_group 2;" ::: "memory")

// ---------------- weight pre-split into planar swizzled image ----------------
__device__ void split_weight(const float* __restrict__ W, int N, int lgK,
                             uint32_t* __restrict__ img, int gtid) {
    const int K = 1 << lgK;
    const int KT = K >> 4;
    const int total = N << lgK;
    uint16_t* img16 = (uint16_t*)img;
    for (int e = gtid; e < total; e += GRIDB * NTHR) {
        int n = e >> lgK, k = e & (K - 1);
        int row = n & 127;
        int sw = ((row >> 2) & 1) << 2;
        int unit = (((k & 15) >> 1) ^ sw);
        size_t base = ((size_t)(n >> 7) * KT + (k >> 4)) * 4096;   // u16 per image
        int idx = row * 16 + unit * 2 + (k & 1);
        float v = W[e];
        img16[base + idx]        = h0u(v);
        img16[base + 2048 + idx] = h1u(v);
    }
}

// ---------------- fp16 3-term MMA GEMM, planar frags, 4-stage cp.async ----------
// Output tile: 128 x 128 at column n0. Segmented virtual K of planar k16-tile images.
__device__ void mma_gemm(uint32_t* sm,
    const uint32_t* __restrict__ A0, const uint32_t* __restrict__ W0, int seg0,
    const uint32_t* __restrict__ A1, const uint32_t* __restrict__ W1,
    int ktB, int ktE, float* __restrict__ Cp, int ldc, int n0)
{
    const int tid  = threadIdx.x;
    const int warp = tid >> 5, lane = tid & 31;
    const int wm = warp >> 2, wn = warp & 3;       // 2 x 4 warp grid, warp tile 64x32
    const int gid = lane >> 2, cc = lane & 3;
    const int sw = (gid >= 4) ? 4 : 0;             // row parity swizzle (uniform/thread)
    const int p0 = cc ^ sw, p1 = (cc ^ sw) ^ 4;
    const uint32_t sbase = (uint32_t)__cvta_generic_to_shared(sm);

    auto issue = [&](int kt, int stage) {
        const uint4* a4; const uint4* w4;
        if (kt < seg0) {
            a4 = (const uint4*)(A0 + (size_t)kt * KTU);
            w4 = (const uint4*)(W0 + (size_t)kt * KTU);
        } else {
            a4 = (const uint4*)(A1 + (size_t)(kt - seg0) * KTU);
            w4 = (const uint4*)(W1 + (size_t)(kt - seg0) * KTU);
        }
        uint32_t sa = sbase + stage * (STG_U * 4);
        uint32_t swp = sa + KTU * 4;
#pragma unroll
        for (int l = 0; l < 2; l++) {
            int s = tid + l * NTHR;                // 512 uint4 per image
            cpa16(sa + s * 16, a4 + s);
            cpa16(swp + s * 16, w4 + s);
        }
    };

    float acc[4][4][4];
#pragma unroll
    for (int i = 0; i < 4; i++)
#pragma unroll
        for (int j = 0; j < 4; j++)
#pragma unroll
            for (int q = 0; q < 4; q++) acc[i][j][q] = 0.f;

    const int nkt = ktE - ktB;
#pragma unroll
    for (int s = 0; s < NSTG - 1; s++) {
        if (s < nkt) issue(ktB + s, s);
        CP_COMMIT();
    }

    for (int kt = ktB; kt < ktE; kt++) {
        CP_WAIT2();
        __syncthreads();   // stage kt ready AND all warps done with stage kt-1
        if (kt + NSTG - 1 < ktE) issue(kt + NSTG - 1, (kt - ktB + NSTG - 1) & (NSTG - 1));
        CP_COMMIT();

        const int st = (kt - ktB) & (NSTG - 1);
        const uint32_t* P0A = sm + st * STG_U;
        const uint32_t* P1A = P0A + 1024;
        const uint32_t* P0W = P0A + 2048;
        const uint32_t* P1W = P0A + 3072;

        uint32_t bs0[4][2], bs1[4][2];
#pragma unroll
        for (int nf = 0; nf < 4; nf++) {
            int n8 = (wn * 32 + nf * 8 + gid) * 8;
            bs0[nf][0] = P0W[n8 + p0];
            bs0[nf][1] = P0W[n8 + p1];
            bs1[nf][0] = P1W[n8 + p0];
            bs1[nf][1] = P1W[n8 + p1];
        }
#pragma unroll
        for (int mf = 0; mf < 4; mf++) {
            int m8a = (wm * 64 + mf * 16 + gid) * 8;
            int m8b = m8a + 64;                    // row m+8
            uint32_t as0_0 = P0A[m8a + p0];
            uint32_t as0_1 = P0A[m8b + p0];
            uint32_t as0_2 = P0A[m8a + p1];
            uint32_t as0_3 = P0A[m8b + p1];
            uint32_t as1_0 = P1A[m8a + p0];
            uint32_t as1_1 = P1A[m8b + p0];
            uint32_t as1_2 = P1A[m8a + p1];
            uint32_t as1_3 = P1A[m8b + p1];
#pragma unroll
            for (int nf = 0; nf < 4; nf++) {
                float* d = acc[mf][nf];
                // 3-term: s0*s0 + s0*s1 + s1*s0 (dropped s1*s1 ~ 2^-22)
                mma_f16(d[0], d[1], d[2], d[3],
                        as0_0, as0_1, as0_2, as0_3, bs0[nf][0], bs0[nf][1]);
                mma_f16(d[0], d[1], d[2], d[3],
                        as0_0, as0_1, as0_2, as0_3, bs1[nf][0], bs1[nf][1]);
                mma_f16(d[0], d[1], d[2], d[3],
                        as1_0, as1_1, as1_2, as1_3, bs0[nf][0], bs0[nf][1]);
            }
        }
    }

#pragma unroll
    for (int mf = 0; mf < 4; mf++) {
        int m = wm * 64 + mf * 16 + gid;
#pragma unroll
        for (int nf = 0; nf < 4; nf++) {
            int col = n0 + wn * 32 + nf * 8 + 2 * cc;
            *(float2*)(Cp + (size_t)m * ldc + col) =
                make_float2(acc[mf][nf][0], acc[mf][nf][1]);
            *(float2*)(Cp + (size_t)(m + 8) * ldc + col) =
                make_float2(acc[mf][nf][2], acc[mf][nf][3]);
        }
    }
}

// ---------------- LSTM gate: vectorized, writes planar split image ----------------
__device__ void gate_phase(const float* __restrict__ bias, float* __restrict__ c,
                           uint32_t* __restrict__ himg, int gtid)
{
    for (int g = gtid; g < (Bsz * Hid) / 4; g += GRIDB * NTHR) {
        int idx = g * 4;
        int b = idx >> 10, j = idx & 1023;         // j multiple of 4
        float4 gi = *(const float4*)&bias[j];
        float4 gf = *(const float4*)&bias[1024 + j];
        float4 gg = *(const float4*)&bias[2048 + j];
        float4 go = *(const float4*)&bias[3072 + j];
        const float* pb = g_part + (size_t)b * G4;
#pragma unroll
        for (int ch = 0; ch < 9; ch++) {
            const float* q = pb + (size_t)ch * Bsz * G4;
            float4 a = *(const float4*)&q[j];
            float4 f = *(const float4*)&q[1024 + j];
            float4 gv = *(const float4*)&q[2048 + j];
            float4 o = *(const float4*)&q[3072 + j];
            gi.x += a.x; gi.y += a.y; gi.z += a.z; gi.w += a.w;
            gf.x += f.x; gf.y += f.y; gf.z += f.z; gf.w += f.w;
            gg.x += gv.x; gg.y += gv.y; gg.z += gv.z; gg.w += gv.w;
            go.x += o.x; go.y += o.y; go.z += o.z; go.w += o.w;
        }
        float4 cv = *(const float4*)&c[idx];
        float4 hv;
        cv.x = fsigm(gf.x) * cv.x + fsigm(gi.x) * ftanh(gg.x);
        cv.y = fsigm(gf.y) * cv.y + fsigm(gi.y) * ftanh(gg.y);
        cv.z = fsigm(gf.z) * cv.z + fsigm(gi.z) * ftanh(gg.z);
        cv.w = fsigm(gf.w) * cv.w + fsigm(gi.w) * ftanh(gg.w);
        hv.x = fsigm(go.x) * ftanh(cv.x);
        hv.y = fsigm(go.y) * ftanh(cv.y);
        hv.z = fsigm(go.z) * ftanh(cv.z);
        hv.w = fsigm(go.w) * ftanh(cv.w);
        *(float4*)&c[idx] = cv;

        // planar write: pairs p, p+1 at physical p^sw (adjacent, 8B aligned)
        int p  = (j & 15) >> 1;                    // 0,2,4,6
        int sb = ((b >> 2) & 1) << 2;
        uint32_t* P0 = himg + (size_t)(j >> 4) * KTU + b * 8;
        uint32_t* P1 = P0 + 1024;
        uint32_t l0 = (uint32_t)h0u(hv.x) | ((uint32_t)h0u(hv.y) << 16);
        uint32_t l1 = (uint32_t)h0u(hv.z) | ((uint32_t)h0u(hv.w) << 16);
        uint32_t r0 = (uint32_t)h1u(hv.x) | ((uint32_t)h1u(hv.y) << 16);
        uint32_t r1 = (uint32_t)h1u(hv.z) | ((uint32_t)h1u(hv.w) << 16);
        *(uint2*)&P0[p ^ sb] = make_uint2(l0, l1);
        *(uint2*)&P1[p ^ sb] = make_uint2(r0, r1);
    }
}

// ---------------- X image writer (token embed, planar split) ----------------
__device__ __forceinline__ void write_x(const float* __restrict__ embeds,
                                        int tok, int b, int tid)
{
    int sb = ((b >> 2) & 1) << 2;
    for (int i = tid; i < Emb / 2; i += NTHR) {    // element pair (2i, 2i+1)
        int col = 2 * i;
        float v0 = 0.f, v1 = 0.f;
        if (tok != 0) {
            float2 vv = *(const float2*)&embeds[(size_t)tok * Emb + col];
            v0 = vv.x; v1 = vv.y;
        }
        uint32_t* P0 = g_Xi + (size_t)(col >> 4) * KTU + b * 8;
        int u = (i & 7) ^ sb;
        P0[u]        = (uint32_t)h0u(v0) | ((uint32_t)h0u(v1) << 16);
        P0[1024 + u] = (uint32_t)h1u(v0) | ((uint32_t)h1u(v1) << 16);
    }
}

// ---------------- params ----------------
struct Params {
    const int*   seq;
    const float* teacher_p;
    const float* embeds;
    const float* W_ih0; const float* W_hh0; const float* b_ih0; const float* b_hh0;
    const float* W_ih1; const float* W_hh1; const float* b_ih1; const float* b_hh1;
    const float* fc_w;  const float* fc_b;
    float* out;
};

// ---------------- the persistent kernel ----------------
__global__ void __launch_bounds__(NTHR, 2) lstm_persist(Params P)
{
    extern __shared__ uint32_t smem_dyn[];
    __shared__ float red_v[NTHR];
    __shared__ int   red_i[NTHR];
    __shared__ int   s_tok;

    const int tid  = threadIdx.x;
    const int blk  = blockIdx.x;
    const int gtid = blk * NTHR + tid;
    unsigned long long lgen = g_gen;   // generation continuation across graph replays

    // ================= setup =================
    for (int idx = gtid; idx < Bsz * Hid; idx += GRIDB * NTHR) {
        g_C0[idx] = 0.f; g_C1[idx] = 0.f;
    }
    for (int idx = gtid; idx < 64 * KTU; idx += GRIDB * NTHR) {
        g_H0i[idx] = 0u; g_H1i[idx] = 0u;
    }
    for (int i = gtid; i < G4; i += GRIDB * NTHR) {
        g_bias0[i] = P.b_ih0[i] + P.b_hh0[i];
        g_bias1[i] = P.b_ih1[i] + P.b_hh1[i];
    }
    split_weight(P.W_ih0, G4,    9,  g_Wih0s, gtid);
    split_weight(P.W_hh0, G4,    10, g_Whh0s, gtid);
    split_weight(P.W_ih1, G4,    10, g_Wih1s, gtid);
    split_weight(P.W_hh1, G4,    10, g_Whh1s, gtid);
    split_weight(P.fc_w,  Vocab, 10, g_fcws,  gtid);

    if (blk < 128) {
        // threefry-2x32, partitionable scheme: bits[i] = o0 ^ o1,
        // (o0,o1) = threefry2x32(key=(0,1), (hi32(i)=0, lo32(i)=i))
        int j = blk * NTHR + tid;
        const unsigned ks0 = 0u, ks1 = 1u, ks2 = 0u ^ 1u ^ 0x1BD11BDAu;
#pragma unroll
        for (int half = 0; half < 2; half++) {
            unsigned idx = (unsigned)j + (unsigned)half * 32768u;
            unsigned x0 = 0u, x1 = idx;
            x0 += ks0; x1 += ks1;
#define R4(a,b,c,d) \
            x0 += x1; x1 = rotl32(x1,a); x1 ^= x0; \
            x0 += x1; x1 = rotl32(x1,b); x1 ^= x0; \
            x0 += x1; x1 = rotl32(x1,c); x1 ^= x0; \
            x0 += x1; x1 = rotl32(x1,d); x1 ^= x0;
            R4(13,15,26,6);   x0 += ks1; x1 += ks2 + 1u;
            R4(17,29,16,24);  x0 += ks2; x1 += ks0 + 2u;
            R4(13,15,26,6);   x0 += ks0; x1 += ks1 + 3u;
            R4(17,29,16,24);  x0 += ks1; x1 += ks2 + 4u;
            R4(13,15,26,6);   x0 += ks2; x1 += ks0 + 5u;
#undef R4
            unsigned bits = x0 ^ x1;
            float p = *P.teacher_p;
            float u = __uint_as_float((bits >> 9) | 0x3f800000u) - 1.0f;
            g_dec[idx] = (u < p) ? 1 : 0;
        }
        // X image for t = 0 (always teacher-forced)
        write_x(P.embeds, P.seq[blk * Tlen], blk, tid);
    }
    grid_sync(lgen);

    // ================= time loop =================
    for (int t = 0; t < Tlen; t++) {
        // ---- layer 0: X@Wih0 + H0@Whh0 (virtual K = 32|64 = 96 k-tiles)
        {
            int nt = blk % 32, chunk = blk / 32;   // 32 N-tiles x 9 chunks
            int kb = chunk * 96 / 9, ke = (chunk + 1) * 96 / 9;
            mma_gemm(smem_dyn,
                     g_Xi,  g_Wih0s + (size_t)nt * 32 * KTU, 32,
                     g_H0i, g_Whh0s + (size_t)nt * 64 * KTU,
                     kb, ke, g_part + (size_t)chunk * Bsz * G4, G4, nt * 128);
        }
        grid_sync(lgen);
        gate_phase(g_bias0, g_C0, g_H0i, gtid);
        grid_sync(lgen);

        // ---- layer 1: H0@Wih1 + H1@Whh1 (virtual K = 64|64 = 128 k-tiles)
        {
            int nt = blk % 32, chunk = blk / 32;
            int kb = chunk * 128 / 9, ke = (chunk + 1) * 128 / 9;
            mma_gemm(smem_dyn,
                     g_H0i, g_Wih1s + (size_t)nt * 64 * KTU, 64,
                     g_H1i, g_Whh1s + (size_t)nt * 64 * KTU,
                     kb, ke, g_part + (size_t)chunk * Bsz * G4, G4, nt * 128);
        }
        grid_sync(lgen);
        gate_phase(g_bias1, g_C1, g_H1i, gtid);
        grid_sync(lgen);

        // ---- logits: H1@fcw (64 k-tiles; 4 N-tiles x 32 chunks x 2 kt = 128 blocks)
        if (blk < 128) {
            int nt = blk & 3, chunk = blk >> 2;
            mma_gemm(smem_dyn,
                     g_H1i, g_fcws + (size_t)nt * 64 * KTU, 64,
                     g_H1i, g_fcws,    // seg1 never reached
                     chunk * 2, chunk * 2 + 2, g_lpart + (size_t)chunk * Bsz * Vocab,
                     Vocab, nt * 128);
        }
        grid_sync(lgen);

        // ---- epilogue: sum LCH partials + bias (float4), write out, argmax, next X
        if (blk < 128) {
            int b = blk;
            float* orow = P.out + ((size_t)b * Tlen + t) * Vocab;
            float bv = -3.402823e38f; int bi = 0;
            for (int n4 = tid; n4 < Vocab / 4; n4 += NTHR) {
                int n = n4 * 4;
                float4 v = *(const float4*)&P.fc_b[n];
#pragma unroll 8
                for (int ch = 0; ch < LCH; ch++) {
                    const float4 p4 = *(const float4*)
                        &g_lpart[(size_t)ch * Bsz * Vocab + b * Vocab + n];
                    v.x += p4.x; v.y += p4.y; v.z += p4.z; v.w += p4.w;
                }
                *(float4*)&orow[n] = v;
                if (v.x > bv) { bv = v.x; bi = n; }
                if (v.y > bv) { bv = v.y; bi = n + 1; }
                if (v.z > bv) { bv = v.z; bi = n + 2; }
                if (v.w > bv) { bv = v.w; bi = n + 3; }
            }
            red_v[tid] = bv; red_i[tid] = bi;
            __syncthreads();
            for (int s = NTHR / 2; s > 0; s >>= 1) {
                if (tid < s) {
                    float v2 = red_v[tid + s]; int i2 = red_i[tid + s];
                    if (v2 > red_v[tid] || (v2 == red_v[tid] && i2 < red_i[tid])) {
                        red_v[tid] = v2; red_i[tid] = i2;
                    }
                }
                __syncthreads();
            }
            if (t + 1 < Tlen) {
                if (tid == 0) {
                    bool teacher = g_dec[(t + 1) * Bsz + b] != 0;
                    s_tok = teacher ? P.seq[b * Tlen + (t + 1)] : red_i[0];
                }
                __syncthreads();
                write_x(P.embeds, s_tok, b, tid);
            }
        }
        grid_sync(lgen);
    }
}

// ---------------- host launch: ONE kernel node, fully graph-capturable ----------------
extern "C" void kernel_launch(void* const* d_in, const int* in_sizes, int n_in,
                              void* d_out, int out_size)
{
    Params P;
    P.seq       = (const int*)d_in[0];
    // d_in[1] = seq_lens (unused by the reference computation)
    P.teacher_p = (const float*)d_in[2];
    P.embeds    = (const float*)d_in[3];
    P.W_ih0     = (const float*)d_in[4];
    P.W_hh0     = (const float*)d_in[5];
    P.b_ih0     = (const float*)d_in[6];
    P.b_hh0     = (const float*)d_in[7];
    P.W_ih1     = (const float*)d_in[8];
    P.W_hh1     = (const float*)d_in[9];
    P.b_ih1     = (const float*)d_in[10];
    P.b_hh1     = (const float*)d_in[11];
    P.fc_w      = (const float*)d_in[12];
    P.fc_b      = (const float*)d_in[13];
    P.out       = (float*)d_out;

    cudaFuncSetAttribute(lstm_persist, cudaFuncAttributeMaxDynamicSharedMemorySize,
                         SMEM_DYN);
    lstm_persist<<<GRIDB, NTHR, SMEM_DYN>>>(P);
}

// round 15
// speedup vs baseline: 2.5781x; 1.1932x over previous
#include <cuda_runtime.h>
#include <cstdint>
#include <cstddef>
#include <cuda_fp16.h>

#define GRIDB 288
#define NTHR  256
#define Bsz   128
#define Tlen  512
#define Vocab 512
#define Emb   512
#define Hid   1024
#define G4    4096

// planar fp16-pair images: per k-tile = plane0 (128x16 u16 s0) + plane1 (s1), 8KB
// row-swizzle: u32-unit u of row r stored at physical unit u ^ (((r>>2)&1)<<2)
#define KTU    2048                  // u32 per k-tile image (2 planes x 1024)
#define NSTG   4                     // cp.async pipeline stages
#define STG_U  (2 * KTU)             // A img + W img per stage (u32)
#define SMEM_DYN (NSTG * STG_U * 4)  // 65536 bytes

#define LCH    32                    // logits partial chunks
// partial chunk buffers: [0..3]=Whh0(4), [4..8]=Wih1(5), [9..13]=Whh1(5)
#define NPART  14

// ---------------- device scratch (static; no runtime allocation) ----------------
__device__ uint32_t g_Wih0s[(size_t)32 * 32 * KTU];   // K=512,  N=4096 (setup only)
__device__ uint32_t g_Whh0s[(size_t)32 * 64 * KTU];   // K=1024, N=4096
__device__ uint32_t g_Wih1s[(size_t)32 * 64 * KTU];
__device__ uint32_t g_Whh1s[(size_t)32 * 64 * KTU];
__device__ uint32_t g_fcws [(size_t)4  * 64 * KTU];   // K=1024, N=512
__device__ uint32_t g_Ei  [(size_t)4  * 32 * KTU];    // emb image (setup only)
__device__ uint32_t g_H0i[(size_t)64 * KTU];
__device__ uint32_t g_H1i[(size_t)64 * KTU];

__device__ float g_EW0[(size_t)Vocab * G4];           // emb @ Wih0^T  (8MB)
__device__ float g_C0[Bsz * Hid];
__device__ float g_C1[Bsz * Hid];
__device__ float g_part[(size_t)NPART * Bsz * G4];    // partial chunk buffers
__device__ float g_lpart[LCH * Bsz * Vocab];          // logits partials
__device__ float g_bias0[G4];
__device__ float g_bias1[G4];
__device__ int   g_tok[Bsz];
__device__ unsigned char g_dec[Tlen * Bsz];

// ---------------- software grid barrier (generation-continued) ----------------
__device__ unsigned long long g_cnt;
__device__ volatile unsigned long long g_gen;

__device__ __forceinline__ void grid_sync(unsigned long long& lgen) {
    __threadfence();
    __syncthreads();
    if (threadIdx.x == 0) {
        lgen += 1ULL;
        unsigned long long a = atomicAdd(&g_cnt, 1ULL) + 1ULL;
        if (a == lgen * (unsigned long long)GRIDB) {
            g_gen = lgen;
            __threadfence();
        } else {
            while (g_gen < lgen) { __nanosleep(16); }
            __threadfence();
        }
    }
    __syncthreads();
}

// ---------------- small helpers ----------------
__device__ __forceinline__ unsigned rotl32(unsigned x, int d) {
    return (x << d) | (x >> (32 - d));
}
__device__ __forceinline__ float fsigm(float x) {
    return __fdividef(1.0f, 1.0f + __expf(-x));
}
__device__ __forceinline__ float ftanh(float x) {
    return __fdividef(2.0f, 1.0f + __expf(-2.0f * x)) - 1.0f;
}
__device__ __forceinline__ unsigned short h0u(float v) {
    return __half_as_ushort(__float2half_rn(v));
}
__device__ __forceinline__ unsigned short h1u(float v) {
    float r = v - __half2float(__float2half_rn(v));
    return __half_as_ushort(__float2half_rn(r));
}

__device__ __forceinline__ void mma_f16(float& d0, float& d1, float& d2, float& d3,
                                        uint32_t a0, uint32_t a1, uint32_t a2, uint32_t a3,
                                        uint32_t b0, uint32_t b1) {
    asm volatile(
        "mma.sync.aligned.m16n8k16.row.col.f32.f16.f16.f32 "
        "{%0,%1,%2,%3}, {%4,%5,%6,%7}, {%8,%9}, {%0,%1,%2,%3};"
        : "+f"(d0), "+f"(d1), "+f"(d2), "+f"(d3)
        : "r"(a0), "r"(a1), "r"(a2), "r"(a3), "r"(b0), "r"(b1));
}

__device__ __forceinline__ void cpa16(uint32_t s, const void* g) {
    asm volatile("cp.async.cg.shared.global [%0], [%1], 16;" :: "r"(s), "l"(g));
}
#define CP_COMMIT() asm volatile("cp.async.commit_group;" ::: "memory")
#define CP_WAIT2()  asm volatile("cp.async.wait_group 2;" ::: "memory")

// ---------------- matrix pre-split into planar swizzled image ----------------
// W: [N, K] row-major; zrow: row index forced to zero (-1 = none)
__device__ void split_weight(const float* __restrict__ W, int N, int lgK,
                             uint32_t* __restrict__ img, int gtid, int zrow) {
    const int K = 1 << lgK;
    const int KT = K >> 4;
    const int total = N << lgK;
    uint16_t* img16 = (uint16_t*)img;
    for (int e = gtid; e < total; e += GRIDB * NTHR) {
        int n = e >> lgK, k = e & (K - 1);
        int row = n & 127;
        int sw = ((row >> 2) & 1) << 2;
        int unit = (((k & 15) >> 1) ^ sw);
        size_t base = ((size_t)(n >> 7) * KT + (k >> 4)) * 4096;   // u16 per image
        int idx = row * 16 + unit * 2 + (k & 1);
        float v = (n == zrow) ? 0.f : W[e];
        img16[base + idx]        = h0u(v);
        img16[base + 2048 + idx] = h1u(v);
    }
}

// ---------------- fp16 3-term MMA GEMM, planar frags, 4-stage cp.async ----------
__device__ void mma_gemm(uint32_t* sm,
    const uint32_t* __restrict__ A0, const uint32_t* __restrict__ W0,
    int ktB, int ktE, float* __restrict__ Cp, int ldc, int n0)
{
    const int tid  = threadIdx.x;
    const int warp = tid >> 5, lane = tid & 31;
    const int wm = warp >> 2, wn = warp & 3;       // 2 x 4 warp grid, warp tile 64x32
    const int gid = lane >> 2, cc = lane & 3;
    const int sw = (gid >= 4) ? 4 : 0;
    const int p0 = cc ^ sw, p1 = (cc ^ sw) ^ 4;
    const uint32_t sbase = (uint32_t)__cvta_generic_to_shared(sm);

    auto issue = [&](int kt, int stage) {
        const uint4* a4 = (const uint4*)(A0 + (size_t)kt * KTU);
        const uint4* w4 = (const uint4*)(W0 + (size_t)kt * KTU);
        uint32_t sa = sbase + stage * (STG_U * 4);
        uint32_t swp = sa + KTU * 4;
#pragma unroll
        for (int l = 0; l < 2; l++) {
            int s = tid + l * NTHR;
            cpa16(sa + s * 16, a4 + s);
            cpa16(swp + s * 16, w4 + s);
        }
    };

    float acc[4][4][4];
#pragma unroll
    for (int i = 0; i < 4; i++)
#pragma unroll
        for (int j = 0; j < 4; j++)
#pragma unroll
            for (int q = 0; q < 4; q++) acc[i][j][q] = 0.f;

    const int nkt = ktE - ktB;
#pragma unroll
    for (int s = 0; s < NSTG - 1; s++) {
        if (s < nkt) issue(ktB + s, s);
        CP_COMMIT();
    }

    for (int kt = ktB; kt < ktE; kt++) {
        CP_WAIT2();
        __syncthreads();   // stage kt ready AND all warps done with stage kt-1
        if (kt + NSTG - 1 < ktE) issue(kt + NSTG - 1, (kt - ktB + NSTG - 1) & (NSTG - 1));
        CP_COMMIT();

        const int st = (kt - ktB) & (NSTG - 1);
        const uint32_t* P0A = sm + st * STG_U;
        const uint32_t* P1A = P0A + 1024;
        const uint32_t* P0W = P0A + 2048;
        const uint32_t* P1W = P0A + 3072;

        uint32_t bs0[4][2], bs1[4][2];
#pragma unroll
        for (int nf = 0; nf < 4; nf++) {
            int n8 = (wn * 32 + nf * 8 + gid) * 8;
            bs0[nf][0] = P0W[n8 + p0];
            bs0[nf][1] = P0W[n8 + p1];
            bs1[nf][0] = P1W[n8 + p0];
            bs1[nf][1] = P1W[n8 + p1];
        }
#pragma unroll
        for (int mf = 0; mf < 4; mf++) {
            int m8a = (wm * 64 + mf * 16 + gid) * 8;
            int m8b = m8a + 64;
            uint32_t as0_0 = P0A[m8a + p0];
            uint32_t as0_1 = P0A[m8b + p0];
            uint32_t as0_2 = P0A[m8a + p1];
            uint32_t as0_3 = P0A[m8b + p1];
            uint32_t as1_0 = P1A[m8a + p0];
            uint32_t as1_1 = P1A[m8b + p0];
            uint32_t as1_2 = P1A[m8a + p1];
            uint32_t as1_3 = P1A[m8b + p1];
#pragma unroll
            for (int nf = 0; nf < 4; nf++) {
                float* d = acc[mf][nf];
                // 3-term: s0*s0 + s0*s1 + s1*s0 (dropped s1*s1 ~ 2^-22)
                mma_f16(d[0], d[1], d[2], d[3],
                        as0_0, as0_1, as0_2, as0_3, bs0[nf][0], bs0[nf][1]);
                mma_f16(d[0], d[1], d[2], d[3],
                        as0_0, as0_1, as0_2, as0_3, bs1[nf][0], bs1[nf][1]);
                mma_f16(d[0], d[1], d[2], d[3],
                        as1_0, as1_1, as1_2, as1_3, bs0[nf][0], bs0[nf][1]);
            }
        }
    }

#pragma unroll
    for (int mf = 0; mf < 4; mf++) {
        int m = wm * 64 + mf * 16 + gid;
#pragma unroll
        for (int nf = 0; nf < 4; nf++) {
            int col = n0 + wn * 32 + nf * 8 + 2 * cc;
            *(float2*)(Cp + (size_t)m * ldc + col) =
                make_float2(acc[mf][nf][0], acc[mf][nf][1]);
            *(float2*)(Cp + (size_t)(m + 8) * ldc + col) =
                make_float2(acc[mf][nf][2], acc[mf][nf][3]);
        }
    }
}

// ---------------- LSTM gates ----------------
// gate0: sum chunks [0..3] + EW0[tok_b] row; write H0 image + C0
__device__ void gate0_phase(const float* __restrict__ bias, float* __restrict__ c,
                            uint32_t* __restrict__ himg, int gtid)
{
    for (int g = gtid; g < (Bsz * Hid) / 4; g += GRIDB * NTHR) {
        int idx = g * 4;
        int b = idx >> 10, j = idx & 1023;
        float4 gi = *(const float4*)&bias[j];
        float4 gf = *(const float4*)&bias[1024 + j];
        float4 gg = *(const float4*)&bias[2048 + j];
        float4 go = *(const float4*)&bias[3072 + j];
        const float* er = g_EW0 + (size_t)g_tok[b] * G4;
        {
            float4 a = *(const float4*)&er[j];
            float4 f = *(const float4*)&er[1024 + j];
            float4 gv = *(const float4*)&er[2048 + j];
            float4 o = *(const float4*)&er[3072 + j];
            gi.x += a.x; gi.y += a.y; gi.z += a.z; gi.w += a.w;
            gf.x += f.x; gf.y += f.y; gf.z += f.z; gf.w += f.w;
            gg.x += gv.x; gg.y += gv.y; gg.z += gv.z; gg.w += gv.w;
            go.x += o.x; go.y += o.y; go.z += o.z; go.w += o.w;
        }
        const float* pb = g_part + (size_t)b * G4;
#pragma unroll
        for (int ch = 0; ch < 4; ch++) {
            const float* q = pb + (size_t)ch * Bsz * G4;
            float4 a = *(const float4*)&q[j];
            float4 f = *(const float4*)&q[1024 + j];
            float4 gv = *(const float4*)&q[2048 + j];
            float4 o = *(const float4*)&q[3072 + j];
            gi.x += a.x; gi.y += a.y; gi.z += a.z; gi.w += a.w;
            gf.x += f.x; gf.y += f.y; gf.z += f.z; gf.w += f.w;
            gg.x += gv.x; gg.y += gv.y; gg.z += gv.z; gg.w += gv.w;
            go.x += o.x; go.y += o.y; go.z += o.z; go.w += o.w;
        }
        float4 cv = *(const float4*)&c[idx];
        float4 hv;
        cv.x = fsigm(gf.x) * cv.x + fsigm(gi.x) * ftanh(gg.x);
        cv.y = fsigm(gf.y) * cv.y + fsigm(gi.y) * ftanh(gg.y);
        cv.z = fsigm(gf.z) * cv.z + fsigm(gi.z) * ftanh(gg.z);
        cv.w = fsigm(gf.w) * cv.w + fsigm(gi.w) * ftanh(gg.w);
        hv.x = fsigm(go.x) * ftanh(cv.x);
        hv.y = fsigm(go.y) * ftanh(cv.y);
        hv.z = fsigm(go.z) * ftanh(cv.z);
        hv.w = fsigm(go.w) * ftanh(cv.w);
        *(float4*)&c[idx] = cv;

        int p  = (j & 15) >> 1;
        int sb = ((b >> 2) & 1) << 2;
        uint32_t* P0 = himg + (size_t)(j >> 4) * KTU + b * 8;
        uint32_t* P1 = P0 + 1024;
        uint32_t l0 = (uint32_t)h0u(hv.x) | ((uint32_t)h0u(hv.y) << 16);
        uint32_t l1 = (uint32_t)h0u(hv.z) | ((uint32_t)h0u(hv.w) << 16);
        uint32_t r0 = (uint32_t)h1u(hv.x) | ((uint32_t)h1u(hv.y) << 16);
        uint32_t r1 = (uint32_t)h1u(hv.z) | ((uint32_t)h1u(hv.w) << 16);
        *(uint2*)&P0[p ^ sb] = make_uint2(l0, l1);
        *(uint2*)&P1[p ^ sb] = make_uint2(r0, r1);
    }
}

// gate1: sum chunks [4..13]; write H1 image + C1
__device__ void gate1_phase(const float* __restrict__ bias, float* __restrict__ c,
                            uint32_t* __restrict__ himg, int gtid)
{
    for (int g = gtid; g < (Bsz * Hid) / 4; g += GRIDB * NTHR) {
        int idx = g * 4;
        int b = idx >> 10, j = idx & 1023;
        float4 gi = *(const float4*)&bias[j];
        float4 gf = *(const float4*)&bias[1024 + j];
        float4 gg = *(const float4*)&bias[2048 + j];
        float4 go = *(const float4*)&bias[3072 + j];
        const float* pb = g_part + (size_t)b * G4;
#pragma unroll
        for (int ch = 4; ch < 14; ch++) {
            const float* q = pb + (size_t)ch * Bsz * G4;
            float4 a = *(const float4*)&q[j];
            float4 f = *(const float4*)&q[1024 + j];
            float4 gv = *(const float4*)&q[2048 + j];
            float4 o = *(const float4*)&q[3072 + j];
            gi.x += a.x; gi.y += a.y; gi.z += a.z; gi.w += a.w;
            gf.x += f.x; gf.y += f.y; gf.z += f.z; gf.w += f.w;
            gg.x += gv.x; gg.y += gv.y; gg.z += gv.z; gg.w += gv.w;
            go.x += o.x; go.y += o.y; go.z += o.z; go.w += o.w;
        }
        float4 cv = *(const float4*)&c[idx];
        float4 hv;
        cv.x = fsigm(gf.x) * cv.x + fsigm(gi.x) * ftanh(gg.x);
        cv.y = fsigm(gf.y) * cv.y + fsigm(gi.y) * ftanh(gg.y);
        cv.z = fsigm(gf.z) * cv.z + fsigm(gi.z) * ftanh(gg.z);
        cv.w = fsigm(gf.w) * cv.w + fsigm(gi.w) * ftanh(gg.w);
        hv.x = fsigm(go.x) * ftanh(cv.x);
        hv.y = fsigm(go.y) * ftanh(cv.y);
        hv.z = fsigm(go.z) * ftanh(cv.z);
        hv.w = fsigm(go.w) * ftanh(cv.w);
        *(float4*)&c[idx] = cv;

        int p  = (j & 15) >> 1;
        int sb = ((b >> 2) & 1) << 2;
        uint32_t* P0 = himg + (size_t)(j >> 4) * KTU + b * 8;
        uint32_t* P1 = P0 + 1024;
        uint32_t l0 = (uint32_t)h0u(hv.x) | ((uint32_t)h0u(hv.y) << 16);
        uint32_t l1 = (uint32_t)h0u(hv.z) | ((uint32_t)h0u(hv.w) << 16);
        uint32_t r0 = (uint32_t)h1u(hv.x) | ((uint32_t)h1u(hv.y) << 16);
        uint32_t r1 = (uint32_t)h1u(hv.z) | ((uint32_t)h1u(hv.w) << 16);
        *(uint2*)&P0[p ^ sb] = make_uint2(l0, l1);
        *(uint2*)&P1[p ^ sb] = make_uint2(r0, r1);
    }
}

// ---------------- params ----------------
struct Params {
    const int*   seq;
    const float* teacher_p;
    const float* embeds;
    const float* W_ih0; const float* W_hh0; const float* b_ih0; const float* b_hh0;
    const float* W_ih1; const float* W_hh1; const float* b_ih1; const float* b_hh1;
    const float* fc_w;  const float* fc_b;
    float* out;
};

// epilogue body: sum logits partials, write out row `trow`, argmax; select token
// for step `tsel` into g_tok (if tsel < Tlen)
__device__ void epilogue(const Params& P, int trow, int tsel,
                         float* red_v, int* red_i, int b, int tid)
{
    float* orow = P.out + ((size_t)b * Tlen + trow) * Vocab;
    float bv = -3.402823e38f; int bi = 0;
    for (int n4 = tid; n4 < Vocab / 4; n4 += NTHR) {
        int n = n4 * 4;
        float4 v = *(const float4*)&P.fc_b[n];
#pragma unroll 8
        for (int ch = 0; ch < LCH; ch++) {
            const float4 p4 = *(const float4*)
                &g_lpart[(size_t)ch * Bsz * Vocab + b * Vocab + n];
            v.x += p4.x; v.y += p4.y; v.z += p4.z; v.w += p4.w;
        }
        *(float4*)&orow[n] = v;
        if (v.x > bv) { bv = v.x; bi = n; }
        if (v.y > bv) { bv = v.y; bi = n + 1; }
        if (v.z > bv) { bv = v.z; bi = n + 2; }
        if (v.w > bv) { bv = v.w; bi = n + 3; }
    }
    red_v[tid] = bv; red_i[tid] = bi;
    __syncthreads();
    for (int s = NTHR / 2; s > 0; s >>= 1) {
        if (tid < s) {
            float v2 = red_v[tid + s]; int i2 = red_i[tid + s];
            if (v2 > red_v[tid] || (v2 == red_v[tid] && i2 < red_i[tid])) {
                red_v[tid] = v2; red_i[tid] = i2;
            }
        }
        __syncthreads();
    }
    if (tsel < Tlen && tid == 0) {
        bool teacher = g_dec[tsel * Bsz + b] != 0;
        g_tok[b] = teacher ? P.seq[b * Tlen + tsel] : red_i[0];
    }
}

// ---------------- the persistent kernel ----------------
__global__ void __launch_bounds__(NTHR, 2) lstm_persist(Params P)
{
    extern __shared__ uint32_t smem_dyn[];
    __shared__ float red_v[NTHR];
    __shared__ int   red_i[NTHR];

    const int tid  = threadIdx.x;
    const int blk  = blockIdx.x;
    const int gtid = blk * NTHR + tid;
    unsigned long long lgen = g_gen;   // generation continuation across graph replays

    // ================= setup =================
    for (int idx = gtid; idx < Bsz * Hid; idx += GRIDB * NTHR) {
        g_C0[idx] = 0.f; g_C1[idx] = 0.f;
    }
    for (int idx = gtid; idx < 64 * KTU; idx += GRIDB * NTHR) {
        g_H0i[idx] = 0u; g_H1i[idx] = 0u;
    }
    // zero partial chunks 0..3 (gate0 @ t=0) and 9..13 (gate1 @ t=0)
    for (int idx = gtid; idx < 4 * Bsz * G4; idx += GRIDB * NTHR)
        g_part[idx] = 0.f;
    for (int idx = gtid; idx < 5 * Bsz * G4; idx += GRIDB * NTHR)
        g_part[(size_t)9 * Bsz * G4 + idx] = 0.f;
    for (int i = gtid; i < G4; i += GRIDB * NTHR) {
        g_bias0[i] = P.b_ih0[i] + P.b_hh0[i];
        g_bias1[i] = P.b_ih1[i] + P.b_hh1[i];
    }
    if (gtid < Bsz) g_tok[gtid] = P.seq[gtid * Tlen];   // t=0 always teacher

    split_weight(P.W_ih0, G4,    9,  g_Wih0s, gtid, -1);
    split_weight(P.W_hh0, G4,    10, g_Whh0s, gtid, -1);
    split_weight(P.W_ih1, G4,    10, g_Wih1s, gtid, -1);
    split_weight(P.W_hh1, G4,    10, g_Whh1s, gtid, -1);
    split_weight(P.fc_w,  Vocab, 10, g_fcws,  gtid, -1);
    split_weight(P.embeds, Vocab, 9, g_Ei,    gtid, 0);   // zero padding row

    if (blk < 128) {
        // threefry-2x32, partitionable scheme: bits[i] = o0 ^ o1,
        // (o0,o1) = threefry2x32(key=(0,1), (hi32(i)=0, lo32(i)=i))
        int j = blk * NTHR + tid;
        const unsigned ks0 = 0u, ks1 = 1u, ks2 = 0u ^ 1u ^ 0x1BD11BDAu;
#pragma unroll
        for (int half = 0; half < 2; half++) {
            unsigned idx = (unsigned)j + (unsigned)half * 32768u;
            unsigned x0 = 0u, x1 = idx;
            x0 += ks0; x1 += ks1;
#define R4(a,b,c,d) \
            x0 += x1; x1 = rotl32(x1,a); x1 ^= x0; \
            x0 += x1; x1 = rotl32(x1,b); x1 ^= x0; \
            x0 += x1; x1 = rotl32(x1,c); x1 ^= x0; \
            x0 += x1; x1 = rotl32(x1,d); x1 ^= x0;
            R4(13,15,26,6);   x0 += ks1; x1 += ks2 + 1u;
            R4(17,29,16,24);  x0 += ks2; x1 += ks0 + 2u;
            R4(13,15,26,6);   x0 += ks0; x1 += ks1 + 3u;
            R4(17,29,16,24);  x0 += ks1; x1 += ks2 + 4u;
            R4(13,15,26,6);   x0 += ks2; x1 += ks0 + 5u;
#undef R4
            unsigned bits = x0 ^ x1;
            float p = *P.teacher_p;
            float u = __uint_as_float((bits >> 9) | 0x3f800000u) - 1.0f;
            g_dec[idx] = (u < p) ? 1 : 0;
        }
    }
    grid_sync(lgen);

    // ---- one-time: EW0 = emb @ Wih0^T (4 M-tiles x 32 N-tiles, full K=512) ----
    if (blk < 128) {
        int mt = blk >> 5, nt = blk & 31;
        mma_gemm(smem_dyn,
                 g_Ei + (size_t)mt * 32 * KTU, g_Wih0s + (size_t)nt * 32 * KTU,
                 0, 32, g_EW0 + (size_t)mt * 128 * G4, G4, nt * 128);
    }
    grid_sync(lgen);

    // ================= time loop (5 phases per step) =================
    for (int t = 0; t < Tlen; t++) {
        // PH1: epilogue(t-1) -> out row t-1, g_tok for step t
        if (t > 0 && blk < 128)
            epilogue(P, t - 1, t, red_v, red_i, blk, tid);
        grid_sync(lgen);

        // PH2: gate0(t) = Whh0 partials [0..3] + EW0[tok] + bias -> H0(t)
        gate0_phase(g_bias0, g_C0, g_H0i, gtid);
        grid_sync(lgen);

        // PH3: Wih1@H0(t) -> chunks 4..8 (160 blks) | Whh0@H0(t) -> chunks 0..3 (128)
        if (blk < 160) {
            int tile = blk % 32, chunk = blk / 32;     // 0..4
            int kb = chunk * 64 / 5, ke = (chunk + 1) * 64 / 5;
            mma_gemm(smem_dyn, g_H0i, g_Wih1s + (size_t)tile * 64 * KTU,
                     kb, ke, g_part + (size_t)(4 + chunk) * Bsz * G4, G4, tile * 128);
        } else {
            int i = blk - 160, tile = i % 32, chunk = i / 32;   // 0..3
            mma_gemm(smem_dyn, g_H0i, g_Whh0s + (size_t)tile * 64 * KTU,
                     chunk * 16, chunk * 16 + 16,
                     g_part + (size_t)chunk * Bsz * G4, G4, tile * 128);
        }
        grid_sync(lgen);

        // PH4: gate1(t) = chunks [4..13] + bias -> H1(t)
        gate1_phase(g_bias1, g_C1, g_H1i, gtid);
        grid_sync(lgen);

        // PH5: logits@H1(t) (128 blks) | Whh1@H1(t) -> chunks 9..13 (160 blks)
        if (blk < 128) {
            int nt = blk & 3, chunk = blk >> 2;        // 0..31
            mma_gemm(smem_dyn, g_H1i, g_fcws + (size_t)nt * 64 * KTU,
                     chunk * 2, chunk * 2 + 2,
                     g_lpart + (size_t)chunk * Bsz * Vocab, Vocab, nt * 128);
        } else {
            int i = blk - 128, tile = i % 32, chunk = i / 32;   // 0..4
            int kb = chunk * 64 / 5, ke = (chunk + 1) * 64 / 5;
            mma_gemm(smem_dyn, g_H1i, g_Whh1s + (size_t)tile * 64 * KTU,
                     kb, ke, g_part + (size_t)(9 + chunk) * Bsz * G4, G4, tile * 128);
        }
        grid_sync(lgen);
    }

    // final epilogue: out row 511 (no next-token select)
    if (blk < 128)
        epilogue(P, Tlen - 1, Tlen, red_v, red_i, blk, tid);
}

// ---------------- host launch: ONE kernel node, fully graph-capturable ----------------
extern "C" void kernel_launch(void* const* d_in, const int* in_sizes, int n_in,
                              void* d_out, int out_size)
{
    Params P;
    P.seq       = (const int*)d_in[0];
    // d_in[1] = seq_lens (unused by the reference computation)
    P.teacher_p = (const float*)d_in[2];
    P.embeds    = (const float*)d_in[3];
    P.W_ih0     = (const float*)d_in[4];
    P.W_hh0     = (const float*)d_in[5];
    P.b_ih0     = (const float*)d_in[6];
    P.b_hh0     = (const float*)d_in[7];
    P.W_ih1     = (const float*)d_in[8];
    P.W_hh1     = (const float*)d_in[9];
    P.b_ih1     = (const float*)d_in[10];
    P.b_hh1     = (const float*)d_in[11];
    P.fc_w      = (const float*)d_in[12];
    P.fc_b      = (const float*)d_in[13];
    P.out       = (float*)d_out;

    cudaFuncSetAttribute(lstm_persist, cudaFuncAttributeMaxDynamicSharedMemorySize,
                         SMEM_DYN);
    lstm_persist<<<GRIDB, NTHR, SMEM_DYN>>>(P);
}

// round 16
// speedup vs baseline: 2.8624x; 1.1103x over previous
#include <cuda_runtime.h>
#include <cstdint>
#include <cstddef>
#include <cuda_fp16.h>

#define GRIDB 288
#define NTHR  256
#define Bsz   128
#define Tlen  512
#define Vocab 512
#define Emb   512
#define Hid   1024
#define G4    4096

// planar fp16-pair images: per k-tile = plane0 (128x16 u16 s0) + plane1 (s1), 8KB
#define KTU    2048                  // u32 per k-tile image (2 planes x 1024)
#define NSTG   4                     // cp.async pipeline stages
#define STG_U  (2 * KTU)             // A img + W img per stage (u32)
#define SMEM_DYN (NSTG * STG_U * 4)  // 65536 bytes

#define LCH    8                     // logits partial chunks
// partial chunk buffers: [0..3]=Whh0(4), [4..8]=Wih1(5), [9..16]=Whh1(8)
#define NPART  17

// ---------------- device scratch (static; no runtime allocation) ----------------
__device__ uint32_t g_Wih0s[(size_t)32 * 32 * KTU];   // K=512,  N=4096 (setup only)
__device__ uint32_t g_Whh0s[(size_t)32 * 64 * KTU];   // K=1024, N=4096
__device__ uint32_t g_Wih1s[(size_t)32 * 64 * KTU];
__device__ uint32_t g_Whh1s[(size_t)32 * 64 * KTU];
__device__ uint32_t g_fcws [(size_t)4  * 64 * KTU];   // K=1024, N=512
__device__ uint32_t g_Ei  [(size_t)4  * 32 * KTU];    // emb image (setup only)
__device__ uint32_t g_H0i[(size_t)64 * KTU];
__device__ uint32_t g_H1i[(size_t)64 * KTU];

__device__ float g_EW0[(size_t)Vocab * G4];           // emb @ Wih0^T  (8MB)
__device__ float g_C0[Bsz * Hid];
__device__ float g_C1[Bsz * Hid];
__device__ float g_part[(size_t)NPART * Bsz * G4];    // partial chunk buffers
__device__ float g_lpart[LCH * Bsz * Vocab];          // logits partials
__device__ float g_bias0[G4];
__device__ float g_bias1[G4];
__device__ int   g_tok[Bsz];
__device__ unsigned char g_dec[Tlen * Bsz];

// ---------------- software grid barrier (generation-continued) ----------------
__device__ unsigned long long g_cnt;
__device__ volatile unsigned long long g_gen;

__device__ __forceinline__ void grid_sync(unsigned long long& lgen) {
    __threadfence();
    __syncthreads();
    if (threadIdx.x == 0) {
        lgen += 1ULL;
        unsigned long long a = atomicAdd(&g_cnt, 1ULL) + 1ULL;
        if (a == lgen * (unsigned long long)GRIDB) {
            g_gen = lgen;
            __threadfence();
        } else {
            while (g_gen < lgen) { __nanosleep(16); }
            __threadfence();
        }
    }
    __syncthreads();
}

// ---------------- small helpers ----------------
__device__ __forceinline__ unsigned rotl32(unsigned x, int d) {
    return (x << d) | (x >> (32 - d));
}
__device__ __forceinline__ unsigned short h0u(float v) {
    return __half_as_ushort(__float2half_rn(v));
}
__device__ __forceinline__ unsigned short h1u(float v) {
    float r = v - __half2float(__float2half_rn(v));
    return __half_as_ushort(__float2half_rn(r));
}

__device__ __forceinline__ float rcpa(float x) {
    float r;
    asm("rcp.approx.f32 %0, %1;" : "=f"(r) : "f"(x));
    return r;
}
// batched reciprocal: 1 MUFU.RCP for 4 values (Montgomery inversion)
__device__ __forceinline__ void rcp4(float a, float b, float c, float d,
                                     float& ra, float& rb, float& rc, float& rd) {
    float p2 = a * b, p3 = p2 * c, p4 = p3 * d;
    float r4 = rcpa(p4);
    rd = r4 * p3;
    float r3 = r4 * d;
    rc = r3 * p2;
    float r2 = r3 * c;
    rb = r2 * a;
    ra = r2 * b;
}
__device__ __forceinline__ float cl16(float x) { return fminf(fmaxf(x, -16.f), 16.f); }
__device__ __forceinline__ float cl8(float x)  { return fminf(fmaxf(x, -8.f), 8.f); }

// LSTM activation for a float4 group: 21 ex2-class + 5 rcp MUFU per 4 elems
__device__ __forceinline__ void lstm_act4(const float* gi, const float* gf,
                                          const float* gg, const float* go,
                                          float* cv, float* hv) {
    float so[4], tc_d[4];
#pragma unroll
    for (int l = 0; l < 4; l++) {
        float di = 1.f + __expf(-cl16(gi[l]));
        float df = 1.f + __expf(-cl16(gf[l]));
        float dg = 1.f + __expf(-2.f * cl8(gg[l]));
        float dq = 1.f + __expf(-cl16(go[l]));
        float si, sf, rg, sq;
        rcp4(di, df, dg, dq, si, sf, rg, sq);
        float tg = 2.f * rg - 1.f;
        cv[l] = sf * cv[l] + si * tg;
        so[l] = sq;
        tc_d[l] = 1.f + __expf(-2.f * cl8(cv[l]));
    }
    float rc0, rc1, rc2, rc3;
    rcp4(tc_d[0], tc_d[1], tc_d[2], tc_d[3], rc0, rc1, rc2, rc3);
    hv[0] = so[0] * (2.f * rc0 - 1.f);
    hv[1] = so[1] * (2.f * rc1 - 1.f);
    hv[2] = so[2] * (2.f * rc2 - 1.f);
    hv[3] = so[3] * (2.f * rc3 - 1.f);
}

__device__ __forceinline__ void mma_f16(float& d0, float& d1, float& d2, float& d3,
                                        uint32_t a0, uint32_t a1, uint32_t a2, uint32_t a3,
                                        uint32_t b0, uint32_t b1) {
    asm volatile(
        "mma.sync.aligned.m16n8k16.row.col.f32.f16.f16.f32 "
        "{%0,%1,%2,%3}, {%4,%5,%6,%7}, {%8,%9}, {%0,%1,%2,%3};"
        : "+f"(d0), "+f"(d1), "+f"(d2), "+f"(d3)
        : "r"(a0), "r"(a1), "r"(a2), "r"(a3), "r"(b0), "r"(b1));
}

__device__ __forceinline__ void cpa16(uint32_t s, const void* g) {
    asm volatile("cp.async.cg.shared.global [%0], [%1], 16;" :: "r"(s), "l"(g));
}
#define CP_COMMIT() asm volatile("cp.async.commit_group;" ::: "memory")
#define CP_WAIT2()  asm volatile("cp.async.wait_group 2;" ::: "memory")

// ---------------- matrix pre-split into planar swizzled image ----------------
__device__ void split_weight(const float* __restrict__ W, int N, int lgK,
                             uint32_t* __restrict__ img, int gtid, int zrow) {
    const int K = 1 << lgK;
    const int KT = K >> 4;
    const int total = N << lgK;
    uint16_t* img16 = (uint16_t*)img;
    for (int e = gtid; e < total; e += GRIDB * NTHR) {
        int n = e >> lgK, k = e & (K - 1);
        int row = n & 127;
        int sw = ((row >> 2) & 1) << 2;
        int unit = (((k & 15) >> 1) ^ sw);
        size_t base = ((size_t)(n >> 7) * KT + (k >> 4)) * 4096;   // u16 per image
        int idx = row * 16 + unit * 2 + (k & 1);
        float v = (n == zrow) ? 0.f : W[e];
        img16[base + idx]        = h0u(v);
        img16[base + 2048 + idx] = h1u(v);
    }
}

// ---------------- fp16 3-term MMA GEMM, planar frags, 4-stage cp.async ----------
__device__ void mma_gemm(uint32_t* sm,
    const uint32_t* __restrict__ A0, const uint32_t* __restrict__ W0,
    int ktB, int ktE, float* __restrict__ Cp, int ldc, int n0)
{
    const int tid  = threadIdx.x;
    const int warp = tid >> 5, lane = tid & 31;
    const int wm = warp >> 2, wn = warp & 3;       // 2 x 4 warp grid, warp tile 64x32
    const int gid = lane >> 2, cc = lane & 3;
    const int sw = (gid >= 4) ? 4 : 0;
    const int p0 = cc ^ sw, p1 = (cc ^ sw) ^ 4;
    const uint32_t sbase = (uint32_t)__cvta_generic_to_shared(sm);

    auto issue = [&](int kt, int stage) {
        const uint4* a4 = (const uint4*)(A0 + (size_t)kt * KTU);
        const uint4* w4 = (const uint4*)(W0 + (size_t)kt * KTU);
        uint32_t sa = sbase + stage * (STG_U * 4);
        uint32_t swp = sa + KTU * 4;
#pragma unroll
        for (int l = 0; l < 2; l++) {
            int s = tid + l * NTHR;
            cpa16(sa + s * 16, a4 + s);
            cpa16(swp + s * 16, w4 + s);
        }
    };

    float acc[4][4][4];
#pragma unroll
    for (int i = 0; i < 4; i++)
#pragma unroll
        for (int j = 0; j < 4; j++)
#pragma unroll
            for (int q = 0; q < 4; q++) acc[i][j][q] = 0.f;

    const int nkt = ktE - ktB;
#pragma unroll
    for (int s = 0; s < NSTG - 1; s++) {
        if (s < nkt) issue(ktB + s, s);
        CP_COMMIT();
    }

    for (int kt = ktB; kt < ktE; kt++) {
        CP_WAIT2();
        __syncthreads();   // stage kt ready AND all warps done with stage kt-1
        if (kt + NSTG - 1 < ktE) issue(kt + NSTG - 1, (kt - ktB + NSTG - 1) & (NSTG - 1));
        CP_COMMIT();

        const int st = (kt - ktB) & (NSTG - 1);
        const uint32_t* P0A = sm + st * STG_U;
        const uint32_t* P1A = P0A + 1024;
        const uint32_t* P0W = P0A + 2048;
        const uint32_t* P1W = P0A + 3072;

        uint32_t bs0[4][2], bs1[4][2];
#pragma unroll
        for (int nf = 0; nf < 4; nf++) {
            int n8 = (wn * 32 + nf * 8 + gid) * 8;
            bs0[nf][0] = P0W[n8 + p0];
            bs0[nf][1] = P0W[n8 + p1];
            bs1[nf][0] = P1W[n8 + p0];
            bs1[nf][1] = P1W[n8 + p1];
        }
#pragma unroll
        for (int mf = 0; mf < 4; mf++) {
            int m8a = (wm * 64 + mf * 16 + gid) * 8;
            int m8b = m8a + 64;
            uint32_t as0_0 = P0A[m8a + p0];
            uint32_t as0_1 = P0A[m8b + p0];
            uint32_t as0_2 = P0A[m8a + p1];
            uint32_t as0_3 = P0A[m8b + p1];
            uint32_t as1_0 = P1A[m8a + p0];
            uint32_t as1_1 = P1A[m8b + p0];
            uint32_t as1_2 = P1A[m8a + p1];
            uint32_t as1_3 = P1A[m8b + p1];
#pragma unroll
            for (int nf = 0; nf < 4; nf++) {
                float* d = acc[mf][nf];
                // 3-term: s0*s0 + s0*s1 + s1*s0 (dropped s1*s1 ~ 2^-22)
                mma_f16(d[0], d[1], d[2], d[3],
                        as0_0, as0_1, as0_2, as0_3, bs0[nf][0], bs0[nf][1]);
                mma_f16(d[0], d[1], d[2], d[3],
                        as0_0, as0_1, as0_2, as0_3, bs1[nf][0], bs1[nf][1]);
                mma_f16(d[0], d[1], d[2], d[3],
                        as1_0, as1_1, as1_2, as1_3, bs0[nf][0], bs0[nf][1]);
            }
        }
    }

#pragma unroll
    for (int mf = 0; mf < 4; mf++) {
        int m = wm * 64 + mf * 16 + gid;
#pragma unroll
        for (int nf = 0; nf < 4; nf++) {
            int col = n0 + wn * 32 + nf * 8 + 2 * cc;
            *(float2*)(Cp + (size_t)m * ldc + col) =
                make_float2(acc[mf][nf][0], acc[mf][nf][1]);
            *(float2*)(Cp + (size_t)(m + 8) * ldc + col) =
                make_float2(acc[mf][nf][2], acc[mf][nf][3]);
        }
    }
}

// ---------------- shared H-image writer ----------------
__device__ __forceinline__ void write_h(uint32_t* himg, int b, int j, const float* hv) {
    int p  = (j & 15) >> 1;
    int sb = ((b >> 2) & 1) << 2;
    uint32_t* P0 = himg + (size_t)(j >> 4) * KTU + b * 8;
    uint32_t* P1 = P0 + 1024;
    uint32_t l0 = (uint32_t)h0u(hv[0]) | ((uint32_t)h0u(hv[1]) << 16);
    uint32_t l1 = (uint32_t)h0u(hv[2]) | ((uint32_t)h0u(hv[3]) << 16);
    uint32_t r0 = (uint32_t)h1u(hv[0]) | ((uint32_t)h1u(hv[1]) << 16);
    uint32_t r1 = (uint32_t)h1u(hv[2]) | ((uint32_t)h1u(hv[3]) << 16);
    *(uint2*)&P0[p ^ sb] = make_uint2(l0, l1);
    *(uint2*)&P1[p ^ sb] = make_uint2(r0, r1);
}

// gate0: sum chunks [0..3] + EW0[tok_b] row; write H0 image + C0
__device__ void gate0_phase(const float* __restrict__ bias, float* __restrict__ c,
                            uint32_t* __restrict__ himg, int gtid)
{
    for (int g = gtid; g < (Bsz * Hid) / 4; g += GRIDB * NTHR) {
        int idx = g * 4;
        int b = idx >> 10, j = idx & 1023;
        float4 gi = *(const float4*)&bias[j];
        float4 gf = *(const float4*)&bias[1024 + j];
        float4 gg = *(const float4*)&bias[2048 + j];
        float4 go = *(const float4*)&bias[3072 + j];
        const float* er = g_EW0 + (size_t)g_tok[b] * G4;
        {
            float4 a = *(const float4*)&er[j];
            float4 f = *(const float4*)&er[1024 + j];
            float4 gv = *(const float4*)&er[2048 + j];
            float4 o = *(const float4*)&er[3072 + j];
            gi.x += a.x; gi.y += a.y; gi.z += a.z; gi.w += a.w;
            gf.x += f.x; gf.y += f.y; gf.z += f.z; gf.w += f.w;
            gg.x += gv.x; gg.y += gv.y; gg.z += gv.z; gg.w += gv.w;
            go.x += o.x; go.y += o.y; go.z += o.z; go.w += o.w;
        }
        const float* pb = g_part + (size_t)b * G4;
#pragma unroll
        for (int ch = 0; ch < 4; ch++) {
            const float* q = pb + (size_t)ch * Bsz * G4;
            float4 a = *(const float4*)&q[j];
            float4 f = *(const float4*)&q[1024 + j];
            float4 gv = *(const float4*)&q[2048 + j];
            float4 o = *(const float4*)&q[3072 + j];
            gi.x += a.x; gi.y += a.y; gi.z += a.z; gi.w += a.w;
            gf.x += f.x; gf.y += f.y; gf.z += f.z; gf.w += f.w;
            gg.x += gv.x; gg.y += gv.y; gg.z += gv.z; gg.w += gv.w;
            go.x += o.x; go.y += o.y; go.z += o.z; go.w += o.w;
        }
        float cv[4], hv[4];
        *(float4*)cv = *(const float4*)&c[idx];
        lstm_act4((const float*)&gi, (const float*)&gf,
                  (const float*)&gg, (const float*)&go, cv, hv);
        *(float4*)&c[idx] = *(float4*)cv;
        write_h(himg, b, j, hv);
    }
}

// gate1: sum chunks [4..16]; write H1 image + C1
__device__ void gate1_phase(const float* __restrict__ bias, float* __restrict__ c,
                            uint32_t* __restrict__ himg, int gtid)
{
    for (int g = gtid; g < (Bsz * Hid) / 4; g += GRIDB * NTHR) {
        int idx = g * 4;
        int b = idx >> 10, j = idx & 1023;
        float4 gi = *(const float4*)&bias[j];
        float4 gf = *(const float4*)&bias[1024 + j];
        float4 gg = *(const float4*)&bias[2048 + j];
        float4 go = *(const float4*)&bias[3072 + j];
        const float* pb = g_part + (size_t)b * G4;
#pragma unroll
        for (int ch = 4; ch < 17; ch++) {
            const float* q = pb + (size_t)ch * Bsz * G4;
            float4 a = *(const float4*)&q[j];
            float4 f = *(const float4*)&q[1024 + j];
            float4 gv = *(const float4*)&q[2048 + j];
            float4 o = *(const float4*)&q[3072 + j];
            gi.x += a.x; gi.y += a.y; gi.z += a.z; gi.w += a.w;
            gf.x += f.x; gf.y += f.y; gf.z += f.z; gf.w += f.w;
            gg.x += gv.x; gg.y += gv.y; gg.z += gv.z; gg.w += gv.w;
            go.x += o.x; go.y += o.y; go.z += o.z; go.w += o.w;
        }
        float cv[4], hv[4];
        *(float4*)cv = *(const float4*)&c[idx];
        lstm_act4((const float*)&gi, (const float*)&gf,
                  (const float*)&gg, (const float*)&go, cv, hv);
        *(float4*)&c[idx] = *(float4*)cv;
        write_h(himg, b, j, hv);
    }
}

// ---------------- params ----------------
struct Params {
    const int*   seq;
    const float* teacher_p;
    const float* embeds;
    const float* W_ih0; const float* W_hh0; const float* b_ih0; const float* b_hh0;
    const float* W_ih1; const float* W_hh1; const float* b_ih1; const float* b_hh1;
    const float* fc_w;  const float* fc_b;
    float* out;
};

// epilogue: sum logits partials, write out row `trow`, argmax; select token for
// step `tsel` into g_tok (if tsel < Tlen)
__device__ void epilogue(const Params& P, int trow, int tsel,
                         float* red_v, int* red_i, int b, int tid)
{
    float* orow = P.out + ((size_t)b * Tlen + trow) * Vocab;
    float bv = -3.402823e38f; int bi = 0;
    for (int n4 = tid; n4 < Vocab / 4; n4 += NTHR) {
        int n = n4 * 4;
        float4 v = *(const float4*)&P.fc_b[n];
#pragma unroll
        for (int ch = 0; ch < LCH; ch++) {
            const float4 p4 = *(const float4*)
                &g_lpart[(size_t)ch * Bsz * Vocab + b * Vocab + n];
            v.x += p4.x; v.y += p4.y; v.z += p4.z; v.w += p4.w;
        }
        *(float4*)&orow[n] = v;
        if (v.x > bv) { bv = v.x; bi = n; }
        if (v.y > bv) { bv = v.y; bi = n + 1; }
        if (v.z > bv) { bv = v.z; bi = n + 2; }
        if (v.w > bv) { bv = v.w; bi = n + 3; }
    }
    red_v[tid] = bv; red_i[tid] = bi;
    __syncthreads();
    for (int s = NTHR / 2; s > 0; s >>= 1) {
        if (tid < s) {
            float v2 = red_v[tid + s]; int i2 = red_i[tid + s];
            if (v2 > red_v[tid] || (v2 == red_v[tid] && i2 < red_i[tid])) {
                red_v[tid] = v2; red_i[tid] = i2;
            }
        }
        __syncthreads();
    }
    if (tsel < Tlen && tid == 0) {
        bool teacher = g_dec[tsel * Bsz + b] != 0;
        g_tok[b] = teacher ? P.seq[b * Tlen + tsel] : red_i[0];
    }
}

// ---------------- the persistent kernel ----------------
__global__ void __launch_bounds__(NTHR, 2) lstm_persist(Params P)
{
    extern __shared__ uint32_t smem_dyn[];
    __shared__ float red_v[NTHR];
    __shared__ int   red_i[NTHR];

    const int tid  = threadIdx.x;
    const int blk  = blockIdx.x;
    const int gtid = blk * NTHR + tid;
    unsigned long long lgen = g_gen;   // generation continuation across graph replays

    // ================= setup =================
    for (int idx = gtid; idx < Bsz * Hid; idx += GRIDB * NTHR) {
        g_C0[idx] = 0.f; g_C1[idx] = 0.f;
    }
    for (int idx = gtid; idx < 64 * KTU; idx += GRIDB * NTHR) {
        g_H0i[idx] = 0u; g_H1i[idx] = 0u;
    }
    // zero partial chunks 0..3 (gate0 @ t=0) and 9..16 (gate1 @ t=0)
    for (int idx = gtid; idx < 4 * Bsz * G4; idx += GRIDB * NTHR)
        g_part[idx] = 0.f;
    for (int idx = gtid; idx < 8 * Bsz * G4; idx += GRIDB * NTHR)
        g_part[(size_t)9 * Bsz * G4 + idx] = 0.f;
    for (int i = gtid; i < G4; i += GRIDB * NTHR) {
        g_bias0[i] = P.b_ih0[i] + P.b_hh0[i];
        g_bias1[i] = P.b_ih1[i] + P.b_hh1[i];
    }
    if (gtid < Bsz) g_tok[gtid] = P.seq[gtid * Tlen];   // t=0 always teacher

    split_weight(P.W_ih0, G4,    9,  g_Wih0s, gtid, -1);
    split_weight(P.W_hh0, G4,    10, g_Whh0s, gtid, -1);
    split_weight(P.W_ih1, G4,    10, g_Wih1s, gtid, -1);
    split_weight(P.W_hh1, G4,    10, g_Whh1s, gtid, -1);
    split_weight(P.fc_w,  Vocab, 10, g_fcws,  gtid, -1);
    split_weight(P.embeds, Vocab, 9, g_Ei,    gtid, 0);   // zero padding row

    if (blk < 128) {
        // threefry-2x32, partitionable scheme: bits[i] = o0 ^ o1,
        // (o0,o1) = threefry2x32(key=(0,1), (hi32(i)=0, lo32(i)=i))
        int j = blk * NTHR + tid;
        const unsigned ks0 = 0u, ks1 = 1u, ks2 = 0u ^ 1u ^ 0x1BD11BDAu;
#pragma unroll
        for (int half = 0; half < 2; half++) {
            unsigned idx = (unsigned)j + (unsigned)half * 32768u;
            unsigned x0 = 0u, x1 = idx;
            x0 += ks0; x1 += ks1;
#define R4(a,b,c,d) \
            x0 += x1; x1 = rotl32(x1,a); x1 ^= x0; \
            x0 += x1; x1 = rotl32(x1,b); x1 ^= x0; \
            x0 += x1; x1 = rotl32(x1,c); x1 ^= x0; \
            x0 += x1; x1 = rotl32(x1,d); x1 ^= x0;
            R4(13,15,26,6);   x0 += ks1; x1 += ks2 + 1u;
            R4(17,29,16,24);  x0 += ks2; x1 += ks0 + 2u;
            R4(13,15,26,6);   x0 += ks0; x1 += ks1 + 3u;
            R4(17,29,16,24);  x0 += ks1; x1 += ks2 + 4u;
            R4(13,15,26,6);   x0 += ks2; x1 += ks0 + 5u;
#undef R4
            unsigned bits = x0 ^ x1;
            float p = *P.teacher_p;
            float u = __uint_as_float((bits >> 9) | 0x3f800000u) - 1.0f;
            g_dec[idx] = (u < p) ? 1 : 0;
        }
    }
    grid_sync(lgen);

    // ---- one-time: EW0 = emb @ Wih0^T (4 M-tiles x 32 N-tiles, full K=512) ----
    if (blk < 128) {
        int mt = blk >> 5, nt = blk & 31;
        mma_gemm(smem_dyn,
                 g_Ei + (size_t)mt * 32 * KTU, g_Wih0s + (size_t)nt * 32 * KTU,
                 0, 32, g_EW0 + (size_t)mt * 128 * G4, G4, nt * 128);
    }
    grid_sync(lgen);

    // ================= time loop (5 phases per step) =================
    for (int t = 0; t < Tlen; t++) {
        // PH1: epilogue(t-1) -> out row t-1, g_tok for step t
        if (t > 0 && blk < 128)
            epilogue(P, t - 1, t, red_v, red_i, blk, tid);
        grid_sync(lgen);

        // PH2: gate0(t) = Whh0 partials [0..3] + EW0[tok] + bias -> H0(t)
        gate0_phase(g_bias0, g_C0, g_H0i, gtid);
        grid_sync(lgen);

        // PH3: Wih1@H0(t) -> chunks 4..8 (160 blks) | Whh0@H0(t) -> chunks 0..3 (128)
        if (blk < 160) {
            int tile = blk % 32, chunk = blk / 32;     // 0..4
            int kb = chunk * 64 / 5, ke = (chunk + 1) * 64 / 5;
            mma_gemm(smem_dyn, g_H0i, g_Wih1s + (size_t)tile * 64 * KTU,
                     kb, ke, g_part + (size_t)(4 + chunk) * Bsz * G4, G4, tile * 128);
        } else {
            int i = blk - 160, tile = i % 32, chunk = i / 32;   // 0..3
            mma_gemm(smem_dyn, g_H0i, g_Whh0s + (size_t)tile * 64 * KTU,
                     chunk * 16, chunk * 16 + 16,
                     g_part + (size_t)chunk * Bsz * G4, G4, tile * 128);
        }
        grid_sync(lgen);

        // PH4: gate1(t) = chunks [4..16] + bias -> H1(t)
        gate1_phase(g_bias1, g_C1, g_H1i, gtid);
        grid_sync(lgen);

        // PH5 (perfectly balanced, 8 kt/block):
        //   Whh1@H1(t) -> chunks 9..16 (256 blks) | logits@H1(t) -> 8 chunks (32 blks)
        if (blk < 256) {
            int tile = blk & 31, chunk = blk >> 5;     // 0..7
            mma_gemm(smem_dyn, g_H1i, g_Whh1s + (size_t)tile * 64 * KTU,
                     chunk * 8, chunk * 8 + 8,
                     g_part + (size_t)(9 + chunk) * Bsz * G4, G4, tile * 128);
        } else {
            int i = blk - 256, nt = i & 3, chunk = i >> 2;      // 0..7
            mma_gemm(smem_dyn, g_H1i, g_fcws + (size_t)nt * 64 * KTU,
                     chunk * 8, chunk * 8 + 8,
                     g_lpart + (size_t)chunk * Bsz * Vocab, Vocab, nt * 128);
        }
        grid_sync(lgen);
    }

    // final epilogue: out row 511 (no next-token select)
    if (blk < 128)
        epilogue(P, Tlen - 1, Tlen, red_v, red_i, blk, tid);
}

// ---------------- host launch: ONE kernel node, fully graph-capturable ----------------
extern "C" void kernel_launch(void* const* d_in, const int* in_sizes, int n_in,
                              void* d_out, int out_size)
{
    Params P;
    P.seq       = (const int*)d_in[0];
    // d_in[1] = seq_lens (unused by the reference computation)
    P.teacher_p = (const float*)d_in[2];
    P.embeds    = (const float*)d_in[3];
    P.W_ih0     = (const float*)d_in[4];
    P.W_hh0     = (const float*)d_in[5];
    P.b_ih0     = (const float*)d_in[6];
    P.b_hh0     = (const float*)d_in[7];
    P.W_ih1     = (const float*)d_in[8];
    P.W_hh1     = (const float*)d_in[9];
    P.b_ih1     = (const float*)d_in[10];
    P.b_hh1     = (const float*)d_in[11];
    P.fc_w      = (const float*)d_in[12];
    P.fc_b      = (const float*)d_in[13];
    P.out       = (float*)d_out;

    cudaFuncSetAttribute(lstm_persist, cudaFuncAttributeMaxDynamicSharedMemorySize,
                         SMEM_DYN);
    lstm_persist<<<GRIDB, NTHR, SMEM_DYN>>>(P);
}